// round 3
// baseline (speedup 1.0000x reference)
#include <cuda_runtime.h>
#include <cuda_bf16.h>
#include <cstdint>
#include <cstddef>

// Problem dims
#define BB 8
#define PP 64
#define TT 512
#define DD 256
#define HH 8
#define DKK 32
#define FFF 512
#define M_TOK (BB*TT*PP)   // 262144

// ---------------- scratch (device globals; allocation-free) ----------------
__device__ float g_xn[(size_t)M_TOK * DD];        // LN1 output, (b,t,p) rows
__device__ float g_q[(size_t)BB*TT*HH*PP*DKK];
__device__ float g_k[(size_t)BB*TT*HH*PP*DKK];
__device__ float g_v[(size_t)BB*TT*HH*PP*DKK];
__device__ float g_bias[(size_t)BB*HH*PP*PP];
__device__ float g_o[(size_t)M_TOK * DD];         // attn out, (b,t,p) rows
__device__ float g_s[(size_t)M_TOK * DD];         // residual pre-LN2
__device__ float g_yn[(size_t)M_TOK * DD];        // LN2 output
__device__ float g_hidden[(size_t)M_TOK * FFF];   // gelu(ff1)

// ---------------- small helpers ----------------
__device__ __forceinline__ uint32_t f2tf(float f) {
    uint32_t r; asm("cvt.rna.tf32.f32 %0, %1;" : "=r"(r) : "f"(f)); return r;
}
__device__ __forceinline__ void mma_tf32(float* c, const uint32_t* a, const uint32_t* b) {
    asm volatile(
        "mma.sync.aligned.m16n8k8.row.col.f32.tf32.tf32.f32 "
        "{%0,%1,%2,%3},{%4,%5,%6,%7},{%8,%9},{%0,%1,%2,%3};"
        : "+f"(c[0]), "+f"(c[1]), "+f"(c[2]), "+f"(c[3])
        : "r"(a[0]), "r"(a[1]), "r"(a[2]), "r"(a[3]), "r"(b[0]), "r"(b[1]));
}
__device__ __forceinline__ uint32_t smem_u32(const void* p) {
    return (uint32_t)__cvta_generic_to_shared(p);
}
__device__ __forceinline__ void cpa16(uint32_t s, const void* g) {
    asm volatile("cp.async.cg.shared.global [%0], [%1], 16;" :: "r"(s), "l"(g));
}

// ---------------- rel-pos bias ----------------
__global__ void relbias_kernel(const float* __restrict__ pos, const float* __restrict__ w_rel) {
    int bp = blockIdx.x;
    int b = bp >> 6, p = bp & 63, q = threadIdx.x;
    const float D2R = 0.017453292519943295f;
    float latp = pos[(size_t)bp*2] * D2R, lonp = pos[(size_t)bp*2+1] * D2R;
    int bq = (b << 6) | q;
    float latq = pos[(size_t)bq*2] * D2R, lonq = pos[(size_t)bq*2+1] * D2R;
    float dlat = latp - latq, dlon = lonp - lonq;
    float dx = dlon * cosf((latp + latq) * 0.5f);
    float dy = dlat;
    float sdlat = sinf(dlat * 0.5f), sdlon = sinf(dlon * 0.5f);
    float a = sdlat*sdlat + cosf(latp)*cosf(latq)*sdlon*sdlon;
    float sq = sqrtf(fmaxf(a, 1e-12f));
    sq = fminf(fmaxf(sq, 0.0f), 1.0f - 1e-7f);
    float dist = 2.0f * 6371.0f * asinf(sq);
    float bear = atan2f(sinf(dlon)*cosf(latq),
                        cosf(latp)*sinf(latq) - sinf(latp)*cosf(latq)*cosf(dlon));
    float r0 = dx, r1 = dy, r2 = dist * (1.0f/500.0f), r3 = sinf(bear);
#pragma unroll
    for (int hh = 0; hh < HH; hh++) {
        float v = r0*w_rel[hh] + r1*w_rel[HH+hh] + r2*w_rel[2*HH+hh] + r3*w_rel[3*HH+hh];
        g_bias[(((size_t)b*HH + hh)*PP + p)*PP + q] = v;
    }
}

// ---------------- LayerNorm kernels (warp per 256-wide row) ----------------
__global__ void __launch_bounds__(256) ln1_kernel(const float* __restrict__ x,
                                                  const float* __restrict__ gw,
                                                  const float* __restrict__ bw) {
    int row = blockIdx.x * 8 + (threadIdx.x >> 5);   // (b,p,t) order
    int lane = threadIdx.x & 31;
    const float* xr = x + (size_t)row * DD;
    float4 v0 = *(const float4*)&xr[lane*4];
    float4 v1 = *(const float4*)&xr[128 + lane*4];
    float s  = v0.x+v0.y+v0.z+v0.w + v1.x+v1.y+v1.z+v1.w;
    float ss = v0.x*v0.x+v0.y*v0.y+v0.z*v0.z+v0.w*v0.w
             + v1.x*v1.x+v1.y*v1.y+v1.z*v1.z+v1.w*v1.w;
#pragma unroll
    for (int o = 16; o; o >>= 1) {
        s  += __shfl_xor_sync(0xffffffffu, s,  o);
        ss += __shfl_xor_sync(0xffffffffu, ss, o);
    }
    float mu = s * (1.0f/256.0f);
    float var = ss * (1.0f/256.0f) - mu*mu;
    float rs = rsqrtf(var + 1e-5f);
    int b = row >> 15, p = (row >> 9) & 63, t = row & 511;
    float* orow = g_xn + (((size_t)(b*TT + t))*PP + p) * DD;
    int d0 = lane*4, d1 = 128 + lane*4;
    float4 gw0 = *(const float4*)&gw[d0], gw1 = *(const float4*)&gw[d1];
    float4 bw0 = *(const float4*)&bw[d0], bw1 = *(const float4*)&bw[d1];
    float4 o0, o1;
    o0.x = (v0.x-mu)*rs*gw0.x + bw0.x; o0.y = (v0.y-mu)*rs*gw0.y + bw0.y;
    o0.z = (v0.z-mu)*rs*gw0.z + bw0.z; o0.w = (v0.w-mu)*rs*gw0.w + bw0.w;
    o1.x = (v1.x-mu)*rs*gw1.x + bw1.x; o1.y = (v1.y-mu)*rs*gw1.y + bw1.y;
    o1.z = (v1.z-mu)*rs*gw1.z + bw1.z; o1.w = (v1.w-mu)*rs*gw1.w + bw1.w;
    *(float4*)&orow[d0] = o0;
    *(float4*)&orow[d1] = o1;
}

__global__ void __launch_bounds__(256) ln2_kernel(const float* __restrict__ gw,
                                                  const float* __restrict__ bw) {
    int row = blockIdx.x * 8 + (threadIdx.x >> 5);
    int lane = threadIdx.x & 31;
    const float* xr = g_s + (size_t)row * DD;
    float4 v0 = *(const float4*)&xr[lane*4];
    float4 v1 = *(const float4*)&xr[128 + lane*4];
    float s  = v0.x+v0.y+v0.z+v0.w + v1.x+v1.y+v1.z+v1.w;
    float ss = v0.x*v0.x+v0.y*v0.y+v0.z*v0.z+v0.w*v0.w
             + v1.x*v1.x+v1.y*v1.y+v1.z*v1.z+v1.w*v1.w;
#pragma unroll
    for (int o = 16; o; o >>= 1) {
        s  += __shfl_xor_sync(0xffffffffu, s,  o);
        ss += __shfl_xor_sync(0xffffffffu, ss, o);
    }
    float mu = s * (1.0f/256.0f);
    float var = ss * (1.0f/256.0f) - mu*mu;
    float rs = rsqrtf(var + 1e-5f);
    float* orow = g_yn + (size_t)row * DD;
    int d0 = lane*4, d1 = 128 + lane*4;
    float4 gw0 = *(const float4*)&gw[d0], gw1 = *(const float4*)&gw[d1];
    float4 bw0 = *(const float4*)&bw[d0], bw1 = *(const float4*)&bw[d1];
    float4 o0, o1;
    o0.x = (v0.x-mu)*rs*gw0.x + bw0.x; o0.y = (v0.y-mu)*rs*gw0.y + bw0.y;
    o0.z = (v0.z-mu)*rs*gw0.z + bw0.z; o0.w = (v0.w-mu)*rs*gw0.w + bw0.w;
    o1.x = (v1.x-mu)*rs*gw1.x + bw1.x; o1.y = (v1.y-mu)*rs*gw1.y + bw1.y;
    o1.z = (v1.z-mu)*rs*gw1.z + bw1.z; o1.w = (v1.w-mu)*rs*gw1.w + bw1.w;
    *(float4*)&orow[d0] = o0;
    *(float4*)&orow[d1] = o1;
}

// ---------------- epilogues ----------------
// EPI 0: QKV scatter    1: +b+res -> g_s    2: gelu -> g_hidden    3: +y -> out(transposed)
template<int EPI>
__device__ __forceinline__ void epi_store(int gm, int gn, float v0, float v1,
                                          const float* __restrict__ biasN,
                                          const float* __restrict__ e0,
                                          float* __restrict__ outp) {
    v0 += biasN[gn]; v1 += biasN[gn+1];
    if constexpr (EPI == 0) {
        int part = gn >> 8, rem = gn & 255, h = rem >> 5, dk = rem & 31;
        int p = gm & 63, bt = gm >> 6;
        float* dst = (part == 0) ? g_q : (part == 1 ? g_k : g_v);
        *(float2*)&dst[(((size_t)bt*HH + h)*PP + p)*DKK + dk] = make_float2(v0, v1);
    } else if constexpr (EPI == 1) {
        int b = gm >> 15, t = (gm >> 6) & 511, p = gm & 63;
        float2 xr = *(const float2*)&e0[(((size_t)(b*PP + p))*TT + t)*DD + gn];
        *(float2*)&g_s[(size_t)gm*DD + gn] = make_float2(v0 + xr.x, v1 + xr.y);
    } else if constexpr (EPI == 2) {
        float g0 = 0.5f * v0 * (1.0f + erff(v0 * 0.70710678118654752f));
        float g1v = 0.5f * v1 * (1.0f + erff(v1 * 0.70710678118654752f));
        *(float2*)&g_hidden[(size_t)gm*FFF + gn] = make_float2(g0, g1v);
    } else {
        float2 y = *(const float2*)&g_yn[(size_t)gm*DD + gn];
        int b = gm >> 15, t = (gm >> 6) & 511, p = gm & 63;
        *(float2*)&outp[(((size_t)(b*PP + p))*TT + t)*DD + gn] = make_float2(y.x + v0, y.y + v1);
    }
}

// ---------------- tf32 GEMM: C[M,N] = A[M,K] * W[K,N], fused epilogue ----------------
// A source is selected statically per EPI (device globals referenced directly;
// no cudaGetSymbolAddress on the host side).
template<int EPI>
__global__ void __launch_bounds__(256, 1) gemm_kernel(
    const float* __restrict__ W,
    const float* __restrict__ biasN, const float* __restrict__ e0,
    float* __restrict__ outp, int M, int N, int K) {
    const float* A = (EPI == 0) ? g_xn : (EPI == 1) ? g_o : (EPI == 2) ? g_yn : g_hidden;
    constexpr int BM = 128, BN = 64, BK = 16;
    __shared__ float As[2][BM][BK + 4];
    __shared__ float Bs[2][BK][BN + 4];
    int tid = threadIdx.x;
    int bm = blockIdx.y * BM, bn = blockIdx.x * BN;

    auto load_stage = [&](int s, int kt) {
#pragma unroll
        for (int i = 0; i < 2; i++) {
            int f = tid + i * 256;
            int row = f >> 2, c4 = (f & 3) * 4;
            cpa16(smem_u32(&As[s][row][c4]), A + (size_t)(bm + row) * K + kt * BK + c4);
        }
        {
            int k = tid >> 4, c4 = (tid & 15) * 4;
            cpa16(smem_u32(&Bs[s][k][c4]), W + (size_t)(kt * BK + k) * N + bn + c4);
        }
        asm volatile("cp.async.commit_group;");
    };

    float acc[2][4][4];
#pragma unroll
    for (int i = 0; i < 2; i++)
#pragma unroll
        for (int j = 0; j < 4; j++)
#pragma unroll
            for (int l = 0; l < 4; l++) acc[i][j][l] = 0.0f;

    int lane = tid & 31, wid = tid >> 5;
    int wm = (wid & 3) * 32, wn = (wid >> 2) * 32;
    int g = lane >> 2, tg = lane & 3;

    int nk = K / BK;
    load_stage(0, 0);
    for (int kt = 0; kt < nk; kt++) {
        if (kt + 1 < nk) {
            load_stage((kt + 1) & 1, kt + 1);
            asm volatile("cp.async.wait_group 1;");
        } else {
            asm volatile("cp.async.wait_group 0;");
        }
        __syncthreads();
        int s = kt & 1;
#pragma unroll
        for (int ks = 0; ks < 2; ks++) {
            int kk = ks * 8;
            uint32_t af[2][4];
#pragma unroll
            for (int mt = 0; mt < 2; mt++) {
                int r = wm + mt * 16 + g;
                af[mt][0] = f2tf(As[s][r    ][kk + tg]);
                af[mt][1] = f2tf(As[s][r + 8][kk + tg]);
                af[mt][2] = f2tf(As[s][r    ][kk + tg + 4]);
                af[mt][3] = f2tf(As[s][r + 8][kk + tg + 4]);
            }
            uint32_t bf[4][2];
#pragma unroll
            for (int nt = 0; nt < 4; nt++) {
                int c = wn + nt * 8 + g;
                bf[nt][0] = f2tf(Bs[s][kk + tg    ][c]);
                bf[nt][1] = f2tf(Bs[s][kk + tg + 4][c]);
            }
#pragma unroll
            for (int mt = 0; mt < 2; mt++)
#pragma unroll
                for (int nt = 0; nt < 4; nt++)
                    mma_tf32(acc[mt][nt], af[mt], bf[nt]);
        }
        __syncthreads();
    }

#pragma unroll
    for (int mt = 0; mt < 2; mt++)
#pragma unroll
        for (int nt = 0; nt < 4; nt++) {
            int gn = bn + wn + nt * 8 + tg * 2;
            int r0 = bm + wm + mt * 16 + g;
            epi_store<EPI>(r0,     gn, acc[mt][nt][0], acc[mt][nt][1], biasN, e0, outp);
            epi_store<EPI>(r0 + 8, gn, acc[mt][nt][2], acc[mt][nt][3], biasN, e0, outp);
        }
}

// ---------------- attention: one CTA per (b,t,h) ----------------
__global__ void __launch_bounds__(128) attn_kernel() {
    __shared__ float Qs[64][36], Ks[64][36], Vs[64][36], Ss[64][68];
    int bth = blockIdx.x;
    int h = bth & 7, bt = bth >> 3, b = bt >> 9;
    size_t base = ((size_t)bt * HH + h) * PP * DKK;
    const float* Qg = g_q + base;
    const float* Kg = g_k + base;
    const float* Vg = g_v + base;
    int tid = threadIdx.x;
    for (int i = tid; i < 512; i += 128) {
        int r = i >> 3, c = (i & 7) * 4;
        *(float4*)&Qs[r][c] = *(const float4*)&Qg[r * 32 + c];
        *(float4*)&Ks[r][c] = *(const float4*)&Kg[r * 32 + c];
        *(float4*)&Vs[r][c] = *(const float4*)&Vg[r * 32 + c];
    }
    __syncthreads();

    int lane = tid & 31, wid = tid >> 5;
    int g = lane >> 2, tg = lane & 3;
    int mb = wid * 16;

    float acc[8][4];
#pragma unroll
    for (int i = 0; i < 8; i++)
#pragma unroll
        for (int j = 0; j < 4; j++) acc[i][j] = 0.0f;

#pragma unroll
    for (int ks = 0; ks < 4; ks++) {
        int kk = ks * 8;
        uint32_t af[4];
        af[0] = f2tf(Qs[mb + g    ][kk + tg]);
        af[1] = f2tf(Qs[mb + g + 8][kk + tg]);
        af[2] = f2tf(Qs[mb + g    ][kk + tg + 4]);
        af[3] = f2tf(Qs[mb + g + 8][kk + tg + 4]);
#pragma unroll
        for (int nt = 0; nt < 8; nt++) {
            uint32_t bf[2];
            bf[0] = f2tf(Ks[nt * 8 + g][kk + tg]);
            bf[1] = f2tf(Ks[nt * 8 + g][kk + tg + 4]);
            mma_tf32(acc[nt], af, bf);
        }
    }

    // softmax (fp32), bias added from global (L2-resident, reused across T)
    int rA = mb + g, rB = rA + 8;
    const float* bA = g_bias + (((size_t)b * HH + h) * PP + rA) * PP;
    const float* bBr = bA + 8 * PP;
    const float sc = 0.17677669529663687f;  // 1/sqrt(32)
    float mA = -1e30f, mB = -1e30f;
#pragma unroll
    for (int nt = 0; nt < 8; nt++) {
        int c = nt * 8 + tg * 2;
        acc[nt][0] = acc[nt][0] * sc + bA[c];
        acc[nt][1] = acc[nt][1] * sc + bA[c + 1];
        acc[nt][2] = acc[nt][2] * sc + bBr[c];
        acc[nt][3] = acc[nt][3] * sc + bBr[c + 1];
        mA = fmaxf(mA, fmaxf(acc[nt][0], acc[nt][1]));
        mB = fmaxf(mB, fmaxf(acc[nt][2], acc[nt][3]));
    }
    mA = fmaxf(mA, __shfl_xor_sync(0xffffffffu, mA, 1));
    mA = fmaxf(mA, __shfl_xor_sync(0xffffffffu, mA, 2));
    mB = fmaxf(mB, __shfl_xor_sync(0xffffffffu, mB, 1));
    mB = fmaxf(mB, __shfl_xor_sync(0xffffffffu, mB, 2));
    float sA = 0.0f, sB = 0.0f;
#pragma unroll
    for (int nt = 0; nt < 8; nt++) {
        acc[nt][0] = expf(acc[nt][0] - mA);
        acc[nt][1] = expf(acc[nt][1] - mA);
        acc[nt][2] = expf(acc[nt][2] - mB);
        acc[nt][3] = expf(acc[nt][3] - mB);
        sA += acc[nt][0] + acc[nt][1];
        sB += acc[nt][2] + acc[nt][3];
    }
    sA += __shfl_xor_sync(0xffffffffu, sA, 1);
    sA += __shfl_xor_sync(0xffffffffu, sA, 2);
    sB += __shfl_xor_sync(0xffffffffu, sB, 1);
    sB += __shfl_xor_sync(0xffffffffu, sB, 2);
    float iA = 1.0f / sA, iB = 1.0f / sB;
#pragma unroll
    for (int nt = 0; nt < 8; nt++) {
        int c = nt * 8 + tg * 2;
        *(float2*)&Ss[rA][c] = make_float2(acc[nt][0] * iA, acc[nt][1] * iA);
        *(float2*)&Ss[rB][c] = make_float2(acc[nt][2] * iB, acc[nt][3] * iB);
    }
    __syncwarp();

    // O = P @ V  (warp owns its own 16 rows of Ss)
    float accO[4][4];
#pragma unroll
    for (int i = 0; i < 4; i++)
#pragma unroll
        for (int j = 0; j < 4; j++) accO[i][j] = 0.0f;
#pragma unroll
    for (int ks = 0; ks < 8; ks++) {
        int kk = ks * 8;
        uint32_t af[4];
        af[0] = f2tf(Ss[mb + g    ][kk + tg]);
        af[1] = f2tf(Ss[mb + g + 8][kk + tg]);
        af[2] = f2tf(Ss[mb + g    ][kk + tg + 4]);
        af[3] = f2tf(Ss[mb + g + 8][kk + tg + 4]);
#pragma unroll
        for (int nt = 0; nt < 4; nt++) {
            uint32_t bf[2];
            bf[0] = f2tf(Vs[kk + tg    ][nt * 8 + g]);
            bf[1] = f2tf(Vs[kk + tg + 4][nt * 8 + g]);
            mma_tf32(accO[nt], af, bf);
        }
    }
#pragma unroll
    for (int nt = 0; nt < 4; nt++) {
        int dk = nt * 8 + tg * 2;
        *(float2*)&g_o[((size_t)bt * PP + rA) * DD + h * 32 + dk] = make_float2(accO[nt][0], accO[nt][1]);
        *(float2*)&g_o[((size_t)bt * PP + rB) * DD + h * 32 + dk] = make_float2(accO[nt][2], accO[nt][3]);
    }
}

// ---------------- launch ----------------
extern "C" void kernel_launch(void* const* d_in, const int* in_sizes, int n_in,
                              void* d_out, int out_size) {
    const float* x     = (const float*)d_in[0];
    const float* pos   = (const float*)d_in[1];
    const float* w_qkv = (const float*)d_in[2];
    const float* b_qkv = (const float*)d_in[3];
    const float* w_out = (const float*)d_in[4];
    const float* b_out = (const float*)d_in[5];
    const float* w_ff1 = (const float*)d_in[6];
    const float* b_ff1 = (const float*)d_in[7];
    const float* w_ff2 = (const float*)d_in[8];
    const float* b_ff2 = (const float*)d_in[9];
    const float* w_rel = (const float*)d_in[10];
    const float* g1    = (const float*)d_in[11];
    const float* be1   = (const float*)d_in[12];
    const float* g2    = (const float*)d_in[13];
    const float* be2   = (const float*)d_in[14];
    float* out = (float*)d_out;

    relbias_kernel<<<BB * PP, 64>>>(pos, w_rel);
    ln1_kernel<<<M_TOK / 8, 256>>>(x, g1, be1);
    gemm_kernel<0><<<dim3(3 * DD / 64, M_TOK / 128), 256>>>(w_qkv, b_qkv, nullptr, nullptr, M_TOK, 3 * DD, DD);
    attn_kernel<<<BB * TT * HH, 128>>>();
    gemm_kernel<1><<<dim3(DD / 64, M_TOK / 128), 256>>>(w_out, b_out, x, nullptr, M_TOK, DD, DD);
    ln2_kernel<<<M_TOK / 8, 256>>>(g2, be2);
    gemm_kernel<2><<<dim3(FFF / 64, M_TOK / 128), 256>>>(w_ff1, b_ff1, nullptr, nullptr, M_TOK, FFF, DD);
    gemm_kernel<3><<<dim3(DD / 64, M_TOK / 128), 256>>>(w_ff2, b_ff2, nullptr, out, M_TOK, DD, FFF);
}

// round 7
// speedup vs baseline: 1.0268x; 1.0268x over previous
#include <cuda_runtime.h>
#include <cuda_bf16.h>
#include <cstdint>
#include <cstddef>

// Problem dims
#define BB 8
#define PP 64
#define TT 512
#define DD 256
#define HH 8
#define DKK 32
#define FFF 512
#define M_TOK (BB*TT*PP)   // 262144

// ---------------- scratch (device globals; allocation-free) ----------------
__device__ float g_xn[(size_t)M_TOK * DD];        // LN1 output (tf32-rounded), (b,t,p) rows
__device__ float g_q[(size_t)BB*TT*HH*PP*DKK];    // tf32-rounded
__device__ float g_k[(size_t)BB*TT*HH*PP*DKK];    // tf32-rounded
__device__ float g_v[(size_t)BB*TT*HH*PP*DKK];    // tf32-rounded
__device__ float g_bias[(size_t)BB*HH*PP*PP];
__device__ float g_o[(size_t)M_TOK * DD];         // attn out (tf32-rounded)
__device__ float g_s[(size_t)M_TOK * DD];         // residual pre-LN2 (fp32)
__device__ float g_yn[(size_t)M_TOK * DD];        // LN2 output (fp32: residual path)
__device__ float g_hidden[(size_t)M_TOK * FFF];   // gelu(ff1) (tf32-rounded)
// tf32-converted weights
__device__ float g_wq[DD*3*DD];
__device__ float g_wo[DD*DD];
__device__ float g_w1[DD*FFF];
__device__ float g_w2[FFF*DD];

// ---------------- small helpers ----------------
__device__ __forceinline__ uint32_t f2tf(float f) {
    uint32_t r; asm("cvt.rna.tf32.f32 %0, %1;" : "=r"(r) : "f"(f)); return r;
}
__device__ __forceinline__ float f2tff(float f) {
    uint32_t r = f2tf(f); return __uint_as_float(r);
}
__device__ __forceinline__ void mma_tf32(float* c, const uint32_t* a, const uint32_t* b) {
    asm volatile(
        "mma.sync.aligned.m16n8k8.row.col.f32.tf32.tf32.f32 "
        "{%0,%1,%2,%3},{%4,%5,%6,%7},{%8,%9},{%0,%1,%2,%3};"
        : "+f"(c[0]), "+f"(c[1]), "+f"(c[2]), "+f"(c[3])
        : "r"(a[0]), "r"(a[1]), "r"(a[2]), "r"(a[3]), "r"(b[0]), "r"(b[1]));
}
__device__ __forceinline__ uint32_t smem_u32(const void* p) {
    return (uint32_t)__cvta_generic_to_shared(p);
}
__device__ __forceinline__ void cpa16(uint32_t s, const void* g) {
    asm volatile("cp.async.cg.shared.global [%0], [%1], 16;" :: "r"(s), "l"(g));
}

// ---------------- weight tf32 pre-conversion ----------------
__global__ void cvtw_kernel(const float* __restrict__ wq, const float* __restrict__ wo,
                            const float* __restrict__ w1, const float* __restrict__ w2) {
    int i = blockIdx.x * 256 + threadIdx.x;
    if (i < 196608)       g_wq[i] = f2tff(wq[i]);
    else if (i < 262144)  g_wo[i - 196608] = f2tff(wo[i - 196608]);
    else if (i < 393216)  g_w1[i - 262144] = f2tff(w1[i - 262144]);
    else                  g_w2[i - 393216] = f2tff(w2[i - 393216]);
}

// ---------------- rel-pos bias ----------------
__global__ void relbias_kernel(const float* __restrict__ pos, const float* __restrict__ w_rel) {
    int bp = blockIdx.x;
    int b = bp >> 6, p = bp & 63, q = threadIdx.x;
    const float D2R = 0.017453292519943295f;
    float latp = pos[(size_t)bp*2] * D2R, lonp = pos[(size_t)bp*2+1] * D2R;
    int bq = (b << 6) | q;
    float latq = pos[(size_t)bq*2] * D2R, lonq = pos[(size_t)bq*2+1] * D2R;
    float dlat = latp - latq, dlon = lonp - lonq;
    float dx = dlon * cosf((latp + latq) * 0.5f);
    float dy = dlat;
    float sdlat = sinf(dlat * 0.5f), sdlon = sinf(dlon * 0.5f);
    float a = sdlat*sdlat + cosf(latp)*cosf(latq)*sdlon*sdlon;
    float sq = sqrtf(fmaxf(a, 1e-12f));
    sq = fminf(fmaxf(sq, 0.0f), 1.0f - 1e-7f);
    float dist = 2.0f * 6371.0f * asinf(sq);
    float bear = atan2f(sinf(dlon)*cosf(latq),
                        cosf(latp)*sinf(latq) - sinf(latp)*cosf(latq)*cosf(dlon));
    float r0 = dx, r1 = dy, r2 = dist * (1.0f/500.0f), r3 = sinf(bear);
#pragma unroll
    for (int hh = 0; hh < HH; hh++) {
        float v = r0*w_rel[hh] + r1*w_rel[HH+hh] + r2*w_rel[2*HH+hh] + r3*w_rel[3*HH+hh];
        g_bias[(((size_t)b*HH + hh)*PP + p)*PP + q] = v;
    }
}

// ---------------- LayerNorm kernels (warp per 256-wide row) ----------------
__global__ void __launch_bounds__(256) ln1_kernel(const float* __restrict__ x,
                                                  const float* __restrict__ gw,
                                                  const float* __restrict__ bw) {
    int row = blockIdx.x * 8 + (threadIdx.x >> 5);   // (b,p,t) order
    int lane = threadIdx.x & 31;
    const float* xr = x + (size_t)row * DD;
    float4 v0 = *(const float4*)&xr[lane*4];
    float4 v1 = *(const float4*)&xr[128 + lane*4];
    float s  = v0.x+v0.y+v0.z+v0.w + v1.x+v1.y+v1.z+v1.w;
    float ss = v0.x*v0.x+v0.y*v0.y+v0.z*v0.z+v0.w*v0.w
             + v1.x*v1.x+v1.y*v1.y+v1.z*v1.z+v1.w*v1.w;
#pragma unroll
    for (int o = 16; o; o >>= 1) {
        s  += __shfl_xor_sync(0xffffffffu, s,  o);
        ss += __shfl_xor_sync(0xffffffffu, ss, o);
    }
    float mu = s * (1.0f/256.0f);
    float var = ss * (1.0f/256.0f) - mu*mu;
    float rs = rsqrtf(var + 1e-5f);
    int b = row >> 15, p = (row >> 9) & 63, t = row & 511;
    float* orow = g_xn + (((size_t)(b*TT + t))*PP + p) * DD;
    int d0 = lane*4, d1 = 128 + lane*4;
    float4 gw0 = *(const float4*)&gw[d0], gw1 = *(const float4*)&gw[d1];
    float4 bw0 = *(const float4*)&bw[d0], bw1 = *(const float4*)&bw[d1];
    float4 o0, o1;
    o0.x = f2tff((v0.x-mu)*rs*gw0.x + bw0.x); o0.y = f2tff((v0.y-mu)*rs*gw0.y + bw0.y);
    o0.z = f2tff((v0.z-mu)*rs*gw0.z + bw0.z); o0.w = f2tff((v0.w-mu)*rs*gw0.w + bw0.w);
    o1.x = f2tff((v1.x-mu)*rs*gw1.x + bw1.x); o1.y = f2tff((v1.y-mu)*rs*gw1.y + bw1.y);
    o1.z = f2tff((v1.z-mu)*rs*gw1.z + bw1.z); o1.w = f2tff((v1.w-mu)*rs*gw1.w + bw1.w);
    *(float4*)&orow[d0] = o0;
    *(float4*)&orow[d1] = o1;
}

__global__ void __launch_bounds__(256) ln2_kernel(const float* __restrict__ gw,
                                                  const float* __restrict__ bw) {
    int row = blockIdx.x * 8 + (threadIdx.x >> 5);
    int lane = threadIdx.x & 31;
    const float* xr = g_s + (size_t)row * DD;
    float4 v0 = *(const float4*)&xr[lane*4];
    float4 v1 = *(const float4*)&xr[128 + lane*4];
    float s  = v0.x+v0.y+v0.z+v0.w + v1.x+v1.y+v1.z+v1.w;
    float ss = v0.x*v0.x+v0.y*v0.y+v0.z*v0.z+v0.w*v0.w
             + v1.x*v1.x+v1.y*v1.y+v1.z*v1.z+v1.w*v1.w;
#pragma unroll
    for (int o = 16; o; o >>= 1) {
        s  += __shfl_xor_sync(0xffffffffu, s,  o);
        ss += __shfl_xor_sync(0xffffffffu, ss, o);
    }
    float mu = s * (1.0f/256.0f);
    float var = ss * (1.0f/256.0f) - mu*mu;
    float rs = rsqrtf(var + 1e-5f);
    float* orow = g_yn + (size_t)row * DD;   // fp32 (residual path)
    int d0 = lane*4, d1 = 128 + lane*4;
    float4 gw0 = *(const float4*)&gw[d0], gw1 = *(const float4*)&gw[d1];
    float4 bw0 = *(const float4*)&bw[d0], bw1 = *(const float4*)&bw[d1];
    float4 o0, o1;
    o0.x = (v0.x-mu)*rs*gw0.x + bw0.x; o0.y = (v0.y-mu)*rs*gw0.y + bw0.y;
    o0.z = (v0.z-mu)*rs*gw0.z + bw0.z; o0.w = (v0.w-mu)*rs*gw0.w + bw0.w;
    o1.x = (v1.x-mu)*rs*gw1.x + bw1.x; o1.y = (v1.y-mu)*rs*gw1.y + bw1.y;
    o1.z = (v1.z-mu)*rs*gw1.z + bw1.z; o1.w = (v1.w-mu)*rs*gw1.w + bw1.w;
    *(float4*)&orow[d0] = o0;
    *(float4*)&orow[d1] = o1;
}

// ---------------- epilogues ----------------
// EPI 0: QKV scatter (tf32)  1: +b+res -> g_s (fp32)  2: gelu -> g_hidden (tf32)  3: +y -> out
template<int EPI>
__device__ __forceinline__ void epi_store(int gm, int gn, float v0, float v1,
                                          const float* __restrict__ biasN,
                                          const float* __restrict__ e0,
                                          float* __restrict__ outp) {
    v0 += biasN[gn]; v1 += biasN[gn+1];
    if constexpr (EPI == 0) {
        int part = gn >> 8, rem = gn & 255, h = rem >> 5, dk = rem & 31;
        int p = gm & 63, bt = gm >> 6;
        float* dst = (part == 0) ? g_q : (part == 1 ? g_k : g_v);
        *(float2*)&dst[(((size_t)bt*HH + h)*PP + p)*DKK + dk] = make_float2(f2tff(v0), f2tff(v1));
    } else if constexpr (EPI == 1) {
        int b = gm >> 15, t = (gm >> 6) & 511, p = gm & 63;
        float2 xr = *(const float2*)&e0[(((size_t)(b*PP + p))*TT + t)*DD + gn];
        *(float2*)&g_s[(size_t)gm*DD + gn] = make_float2(v0 + xr.x, v1 + xr.y);
    } else if constexpr (EPI == 2) {
        float g0 = 0.5f * v0 * (1.0f + erff(v0 * 0.70710678118654752f));
        float g1v = 0.5f * v1 * (1.0f + erff(v1 * 0.70710678118654752f));
        *(float2*)&g_hidden[(size_t)gm*FFF + gn] = make_float2(f2tff(g0), f2tff(g1v));
    } else {
        float2 y = *(const float2*)&g_yn[(size_t)gm*DD + gn];
        int b = gm >> 15, t = (gm >> 6) & 511, p = gm & 63;
        *(float2*)&outp[(((size_t)(b*PP + p))*TT + t)*DD + gn] = make_float2(y.x + v0, y.y + v1);
    }
}

// ---------------- tf32 GEMM: C[M,N] = A[M,K] * W[K,N], fused epilogue ----------------
// Same 2-stage / BM=128 / BN=64 structure as the passing Round-3 kernel; inner
// loops are cvt-free (operands pre-rounded to tf32) except EPI==2's A side.
template<int EPI>
__global__ void __launch_bounds__(256, 1) gemm_kernel(
    const float* __restrict__ biasN, const float* __restrict__ e0,
    float* __restrict__ outp, int M, int N, int K) {
    const float* A = (EPI == 0) ? g_xn : (EPI == 1) ? g_o : (EPI == 2) ? g_yn : g_hidden;
    const float* W = (EPI == 0) ? g_wq : (EPI == 1) ? g_wo : (EPI == 2) ? g_w1 : g_w2;
    constexpr int BM = 128, BN = 64, BK = 16;
    __shared__ float As[2][BM][BK + 4];   // stride 20 (mod 32 = 20): conflict-free A frags
    __shared__ float Bs[2][BK][BN + 8];   // stride 72 (mod 32 = 8): conflict-free B frags
    int tid = threadIdx.x;
    int bm = blockIdx.y * BM, bn = blockIdx.x * BN;

    auto load_stage = [&](int s, int kt) {
#pragma unroll
        for (int i = 0; i < 2; i++) {
            int f = tid + i * 256;
            int row = f >> 2, c4 = (f & 3) * 4;
            cpa16(smem_u32(&As[s][row][c4]), A + (size_t)(bm + row) * K + kt * BK + c4);
        }
        {
            int k = tid >> 4, c4 = (tid & 15) * 4;
            cpa16(smem_u32(&Bs[s][k][c4]), W + (size_t)(kt * BK + k) * N + bn + c4);
        }
        asm volatile("cp.async.commit_group;");
    };

    float acc[2][4][4];
#pragma unroll
    for (int i = 0; i < 2; i++)
#pragma unroll
        for (int j = 0; j < 4; j++)
#pragma unroll
            for (int l = 0; l < 4; l++) acc[i][j][l] = 0.0f;

    int lane = tid & 31, wid = tid >> 5;
    int wm = (wid & 3) * 32, wn = (wid >> 2) * 32;
    int g = lane >> 2, tg = lane & 3;

    int nk = K / BK;
    load_stage(0, 0);
    for (int kt = 0; kt < nk; kt++) {
        if (kt + 1 < nk) {
            load_stage((kt + 1) & 1, kt + 1);
            asm volatile("cp.async.wait_group 1;");
        } else {
            asm volatile("cp.async.wait_group 0;");
        }
        __syncthreads();
        int s = kt & 1;
#pragma unroll
        for (int ks = 0; ks < 2; ks++) {
            int kk = ks * 8;
            uint32_t af[2][4];
#pragma unroll
            for (int mt = 0; mt < 2; mt++) {
                int r = wm + mt * 16 + g;
                float a0 = As[s][r    ][kk + tg];
                float a1 = As[s][r + 8][kk + tg];
                float a2 = As[s][r    ][kk + tg + 4];
                float a3 = As[s][r + 8][kk + tg + 4];
                if constexpr (EPI == 2) {
                    af[mt][0] = f2tf(a0); af[mt][1] = f2tf(a1);
                    af[mt][2] = f2tf(a2); af[mt][3] = f2tf(a3);
                } else {
                    af[mt][0] = __float_as_uint(a0); af[mt][1] = __float_as_uint(a1);
                    af[mt][2] = __float_as_uint(a2); af[mt][3] = __float_as_uint(a3);
                }
            }
            uint32_t bf[4][2];
#pragma unroll
            for (int nt = 0; nt < 4; nt++) {
                int c = wn + nt * 8 + g;
                bf[nt][0] = __float_as_uint(Bs[s][kk + tg    ][c]);
                bf[nt][1] = __float_as_uint(Bs[s][kk + tg + 4][c]);
            }
#pragma unroll
            for (int mt = 0; mt < 2; mt++)
#pragma unroll
                for (int nt = 0; nt < 4; nt++)
                    mma_tf32(acc[mt][nt], af[mt], bf[nt]);
        }
        __syncthreads();
    }

#pragma unroll
    for (int mt = 0; mt < 2; mt++)
#pragma unroll
        for (int nt = 0; nt < 4; nt++) {
            int gn = bn + wn + nt * 8 + tg * 2;
            int r0 = bm + wm + mt * 16 + g;
            epi_store<EPI>(r0,     gn, acc[mt][nt][0], acc[mt][nt][1], biasN, e0, outp);
            epi_store<EPI>(r0 + 8, gn, acc[mt][nt][2], acc[mt][nt][3], biasN, e0, outp);
        }
}

// ---------------- attention: one CTA per (b,t,h) ----------------
__global__ void __launch_bounds__(128) attn_kernel() {
    __shared__ float Qs[64][36], Ks[64][36], Vs[64][36], Ss[64][68];
    int bth = blockIdx.x;
    int h = bth & 7, bt = bth >> 3, b = bt >> 9;
    size_t base = ((size_t)bt * HH + h) * PP * DKK;
    const float* Qg = g_q + base;
    const float* Kg = g_k + base;
    const float* Vg = g_v + base;
    int tid = threadIdx.x;
    for (int i = tid; i < 512; i += 128) {
        int r = i >> 3, c = (i & 7) * 4;
        *(float4*)&Qs[r][c] = *(const float4*)&Qg[r * 32 + c];
        *(float4*)&Ks[r][c] = *(const float4*)&Kg[r * 32 + c];
        *(float4*)&Vs[r][c] = *(const float4*)&Vg[r * 32 + c];
    }
    __syncthreads();

    int lane = tid & 31, wid = tid >> 5;
    int g = lane >> 2, tg = lane & 3;
    int mb = wid * 16;

    float acc[8][4];
#pragma unroll
    for (int i = 0; i < 8; i++)
#pragma unroll
        for (int j = 0; j < 4; j++) acc[i][j] = 0.0f;

#pragma unroll
    for (int ks = 0; ks < 4; ks++) {
        int kk = ks * 8;
        uint32_t af[4];
        af[0] = __float_as_uint(Qs[mb + g    ][kk + tg]);
        af[1] = __float_as_uint(Qs[mb + g + 8][kk + tg]);
        af[2] = __float_as_uint(Qs[mb + g    ][kk + tg + 4]);
        af[3] = __float_as_uint(Qs[mb + g + 8][kk + tg + 4]);
#pragma unroll
        for (int nt = 0; nt < 8; nt++) {
            uint32_t bf[2];
            bf[0] = __float_as_uint(Ks[nt * 8 + g][kk + tg]);
            bf[1] = __float_as_uint(Ks[nt * 8 + g][kk + tg + 4]);
            mma_tf32(acc[nt], af, bf);
        }
    }

    // softmax (fp32), bias from global (L2-resident, reused across T)
    int rA = mb + g, rB = rA + 8;
    const float* bA = g_bias + (((size_t)b * HH + h) * PP + rA) * PP;
    const float* bBr = bA + 8 * PP;
    const float sc = 0.17677669529663687f;  // 1/sqrt(32)
    float mA = -1e30f, mB = -1e30f;
#pragma unroll
    for (int nt = 0; nt < 8; nt++) {
        int c = nt * 8 + tg * 2;
        acc[nt][0] = acc[nt][0] * sc + bA[c];
        acc[nt][1] = acc[nt][1] * sc + bA[c + 1];
        acc[nt][2] = acc[nt][2] * sc + bBr[c];
        acc[nt][3] = acc[nt][3] * sc + bBr[c + 1];
        mA = fmaxf(mA, fmaxf(acc[nt][0], acc[nt][1]));
        mB = fmaxf(mB, fmaxf(acc[nt][2], acc[nt][3]));
    }
    mA = fmaxf(mA, __shfl_xor_sync(0xffffffffu, mA, 1));
    mA = fmaxf(mA, __shfl_xor_sync(0xffffffffu, mA, 2));
    mB = fmaxf(mB, __shfl_xor_sync(0xffffffffu, mB, 1));
    mB = fmaxf(mB, __shfl_xor_sync(0xffffffffu, mB, 2));
    float sA = 0.0f, sB = 0.0f;
#pragma unroll
    for (int nt = 0; nt < 8; nt++) {
        acc[nt][0] = expf(acc[nt][0] - mA);
        acc[nt][1] = expf(acc[nt][1] - mA);
        acc[nt][2] = expf(acc[nt][2] - mB);
        acc[nt][3] = expf(acc[nt][3] - mB);
        sA += acc[nt][0] + acc[nt][1];
        sB += acc[nt][2] + acc[nt][3];
    }
    sA += __shfl_xor_sync(0xffffffffu, sA, 1);
    sA += __shfl_xor_sync(0xffffffffu, sA, 2);
    sB += __shfl_xor_sync(0xffffffffu, sB, 1);
    sB += __shfl_xor_sync(0xffffffffu, sB, 2);
    float iA = 1.0f / sA, iB = 1.0f / sB;
#pragma unroll
    for (int nt = 0; nt < 8; nt++) {
        int c = nt * 8 + tg * 2;
        *(float2*)&Ss[rA][c] = make_float2(f2tff(acc[nt][0] * iA), f2tff(acc[nt][1] * iA));
        *(float2*)&Ss[rB][c] = make_float2(f2tff(acc[nt][2] * iB), f2tff(acc[nt][3] * iB));
    }
    __syncwarp();

    // O = P @ V  (warp owns its own 16 rows of Ss)
    float accO[4][4];
#pragma unroll
    for (int i = 0; i < 4; i++)
#pragma unroll
        for (int j = 0; j < 4; j++) accO[i][j] = 0.0f;
#pragma unroll
    for (int ks = 0; ks < 8; ks++) {
        int kk = ks * 8;
        uint32_t af[4];
        af[0] = __float_as_uint(Ss[mb + g    ][kk + tg]);
        af[1] = __float_as_uint(Ss[mb + g + 8][kk + tg]);
        af[2] = __float_as_uint(Ss[mb + g    ][kk + tg + 4]);
        af[3] = __float_as_uint(Ss[mb + g + 8][kk + tg + 4]);
#pragma unroll
        for (int nt = 0; nt < 4; nt++) {
            uint32_t bf[2];
            bf[0] = __float_as_uint(Vs[kk + tg    ][nt * 8 + g]);
            bf[1] = __float_as_uint(Vs[kk + tg + 4][nt * 8 + g]);
            mma_tf32(accO[nt], af, bf);
        }
    }
#pragma unroll
    for (int nt = 0; nt < 4; nt++) {
        int dk = nt * 8 + tg * 2;
        *(float2*)&g_o[((size_t)bt * PP + rA) * DD + h * 32 + dk] =
            make_float2(f2tff(accO[nt][0]), f2tff(accO[nt][1]));
        *(float2*)&g_o[((size_t)bt * PP + rB) * DD + h * 32 + dk] =
            make_float2(f2tff(accO[nt][2]), f2tff(accO[nt][3]));
    }
}

// ---------------- launch ----------------
extern "C" void kernel_launch(void* const* d_in, const int* in_sizes, int n_in,
                              void* d_out, int out_size) {
    const float* x     = (const float*)d_in[0];
    const float* pos   = (const float*)d_in[1];
    const float* w_qkv = (const float*)d_in[2];
    const float* b_qkv = (const float*)d_in[3];
    const float* w_out = (const float*)d_in[4];
    const float* b_out = (const float*)d_in[5];
    const float* w_ff1 = (const float*)d_in[6];
    const float* b_ff1 = (const float*)d_in[7];
    const float* w_ff2 = (const float*)d_in[8];
    const float* b_ff2 = (const float*)d_in[9];
    const float* w_rel = (const float*)d_in[10];
    const float* g1    = (const float*)d_in[11];
    const float* be1   = (const float*)d_in[12];
    const float* g2    = (const float*)d_in[13];
    const float* be2   = (const float*)d_in[14];
    float* out = (float*)d_out;

    cvtw_kernel<<<2048, 256>>>(w_qkv, w_out, w_ff1, w_ff2);
    relbias_kernel<<<BB * PP, 64>>>(pos, w_rel);
    ln1_kernel<<<M_TOK / 8, 256>>>(x, g1, be1);
    gemm_kernel<0><<<dim3(3 * DD / 64, M_TOK / 128), 256>>>(b_qkv, nullptr, nullptr, M_TOK, 3 * DD, DD);
    attn_kernel<<<BB * TT * HH, 128>>>();
    gemm_kernel<1><<<dim3(DD / 64, M_TOK / 128), 256>>>(b_out, x, nullptr, M_TOK, DD, DD);
    ln2_kernel<<<M_TOK / 8, 256>>>(g2, be2);
    gemm_kernel<2><<<dim3(FFF / 64, M_TOK / 128), 256>>>(b_ff1, nullptr, nullptr, M_TOK, FFF, DD);
    gemm_kernel<3><<<dim3(DD / 64, M_TOK / 128), 256>>>(b_ff2, nullptr, out, M_TOK, DD, FFF);
}

// round 10
// speedup vs baseline: 1.3508x; 1.3155x over previous
#include <cuda_runtime.h>
#include <cuda_bf16.h>
#include <cstdint>
#include <cstddef>

// Problem dims
#define BB 8
#define PP 64
#define TT 512
#define DD 256
#define HH 8
#define DKK 32
#define FFF 512
#define M_TOK (BB*TT*PP)   // 262144

// ---------------- scratch (device globals; allocation-free) ----------------
__device__ float g_xn[(size_t)M_TOK * DD];        // LN1 output (tf32-rounded), (b,t,p) rows
__device__ float g_q[(size_t)BB*TT*HH*PP*DKK];    // tf32-rounded
__device__ float g_k[(size_t)BB*TT*HH*PP*DKK];    // tf32-rounded
__device__ float g_v[(size_t)BB*TT*HH*PP*DKK];    // tf32-rounded
__device__ float g_bias[(size_t)BB*HH*PP*PP];
__device__ float g_o[(size_t)M_TOK * DD];         // attn out (tf32-rounded)
__device__ float g_s[(size_t)M_TOK * DD];         // residual pre-LN2 (fp32)
__device__ float g_yn[(size_t)M_TOK * DD];        // LN2 output (fp32: residual path)
__device__ float g_hidden[(size_t)M_TOK * FFF];   // gelu(ff1) (tf32-rounded)
// tf32-converted weights
__device__ float g_wq[DD*3*DD];
__device__ float g_wo[DD*DD];
__device__ float g_w1[DD*FFF];
__device__ float g_w2[FFF*DD];

// ---------------- small helpers ----------------
__device__ __forceinline__ uint32_t f2tf(float f) {
    uint32_t r; asm("cvt.rna.tf32.f32 %0, %1;" : "=r"(r) : "f"(f)); return r;
}
__device__ __forceinline__ float f2tff(float f) {
    uint32_t r = f2tf(f); return __uint_as_float(r);
}
__device__ __forceinline__ void mma_tf32(float* c, const uint32_t* a, const uint32_t* b) {
    asm volatile(
        "mma.sync.aligned.m16n8k8.row.col.f32.tf32.tf32.f32 "
        "{%0,%1,%2,%3},{%4,%5,%6,%7},{%8,%9},{%0,%1,%2,%3};"
        : "+f"(c[0]), "+f"(c[1]), "+f"(c[2]), "+f"(c[3])
        : "r"(a[0]), "r"(a[1]), "r"(a[2]), "r"(a[3]), "r"(b[0]), "r"(b[1]));
}
__device__ __forceinline__ uint32_t smem_u32(const void* p) {
    return (uint32_t)__cvta_generic_to_shared(p);
}
__device__ __forceinline__ void cpa16(uint32_t s, const void* g) {
    asm volatile("cp.async.cg.shared.global [%0], [%1], 16;" :: "r"(s), "l"(g));
}

// ---------------- weight tf32 pre-conversion ----------------
__global__ void cvtw_kernel(const float* __restrict__ wq, const float* __restrict__ wo,
                            const float* __restrict__ w1, const float* __restrict__ w2) {
    int i = blockIdx.x * 256 + threadIdx.x;
    if (i < 196608)       g_wq[i] = f2tff(wq[i]);
    else if (i < 262144)  g_wo[i - 196608] = f2tff(wo[i - 196608]);
    else if (i < 393216)  g_w1[i - 262144] = f2tff(w1[i - 262144]);
    else                  g_w2[i - 393216] = f2tff(w2[i - 393216]);
}

// ---------------- rel-pos bias ----------------
__global__ void relbias_kernel(const float* __restrict__ pos, const float* __restrict__ w_rel) {
    int bp = blockIdx.x;
    int b = bp >> 6, p = bp & 63, q = threadIdx.x;
    const float D2R = 0.017453292519943295f;
    float latp = pos[(size_t)bp*2] * D2R, lonp = pos[(size_t)bp*2+1] * D2R;
    int bq = (b << 6) | q;
    float latq = pos[(size_t)bq*2] * D2R, lonq = pos[(size_t)bq*2+1] * D2R;
    float dlat = latp - latq, dlon = lonp - lonq;
    float dx = dlon * cosf((latp + latq) * 0.5f);
    float dy = dlat;
    float sdlat = sinf(dlat * 0.5f), sdlon = sinf(dlon * 0.5f);
    float a = sdlat*sdlat + cosf(latp)*cosf(latq)*sdlon*sdlon;
    float sq = sqrtf(fmaxf(a, 1e-12f));
    sq = fminf(fmaxf(sq, 0.0f), 1.0f - 1e-7f);
    float dist = 2.0f * 6371.0f * asinf(sq);
    float bear = atan2f(sinf(dlon)*cosf(latq),
                        cosf(latp)*sinf(latq) - sinf(latp)*cosf(latq)*cosf(dlon));
    float r0 = dx, r1 = dy, r2 = dist * (1.0f/500.0f), r3 = sinf(bear);
#pragma unroll
    for (int hh = 0; hh < HH; hh++) {
        float v = r0*w_rel[hh] + r1*w_rel[HH+hh] + r2*w_rel[2*HH+hh] + r3*w_rel[3*HH+hh];
        g_bias[(((size_t)b*HH + hh)*PP + p)*PP + q] = v;
    }
}

// ---------------- LayerNorm kernels (warp per 256-wide row) ----------------
__global__ void __launch_bounds__(256) ln1_kernel(const float* __restrict__ x,
                                                  const float* __restrict__ gw,
                                                  const float* __restrict__ bw) {
    int row = blockIdx.x * 8 + (threadIdx.x >> 5);   // (b,p,t) order
    int lane = threadIdx.x & 31;
    const float* xr = x + (size_t)row * DD;
    float4 v0 = *(const float4*)&xr[lane*4];
    float4 v1 = *(const float4*)&xr[128 + lane*4];
    float s  = v0.x+v0.y+v0.z+v0.w + v1.x+v1.y+v1.z+v1.w;
    float ss = v0.x*v0.x+v0.y*v0.y+v0.z*v0.z+v0.w*v0.w
             + v1.x*v1.x+v1.y*v1.y+v1.z*v1.z+v1.w*v1.w;
#pragma unroll
    for (int o = 16; o; o >>= 1) {
        s  += __shfl_xor_sync(0xffffffffu, s,  o);
        ss += __shfl_xor_sync(0xffffffffu, ss, o);
    }
    float mu = s * (1.0f/256.0f);
    float var = ss * (1.0f/256.0f) - mu*mu;
    float rs = rsqrtf(var + 1e-5f);
    int b = row >> 15, p = (row >> 9) & 63, t = row & 511;
    float* orow = g_xn + (((size_t)(b*TT + t))*PP + p) * DD;
    int d0 = lane*4, d1 = 128 + lane*4;
    float4 gw0 = *(const float4*)&gw[d0], gw1 = *(const float4*)&gw[d1];
    float4 bw0 = *(const float4*)&bw[d0], bw1 = *(const float4*)&bw[d1];
    float4 o0, o1;
    o0.x = f2tff((v0.x-mu)*rs*gw0.x + bw0.x); o0.y = f2tff((v0.y-mu)*rs*gw0.y + bw0.y);
    o0.z = f2tff((v0.z-mu)*rs*gw0.z + bw0.z); o0.w = f2tff((v0.w-mu)*rs*gw0.w + bw0.w);
    o1.x = f2tff((v1.x-mu)*rs*gw1.x + bw1.x); o1.y = f2tff((v1.y-mu)*rs*gw1.y + bw1.y);
    o1.z = f2tff((v1.z-mu)*rs*gw1.z + bw1.z); o1.w = f2tff((v1.w-mu)*rs*gw1.w + bw1.w);
    *(float4*)&orow[d0] = o0;
    *(float4*)&orow[d1] = o1;
}

__global__ void __launch_bounds__(256) ln2_kernel(const float* __restrict__ gw,
                                                  const float* __restrict__ bw) {
    int row = blockIdx.x * 8 + (threadIdx.x >> 5);
    int lane = threadIdx.x & 31;
    const float* xr = g_s + (size_t)row * DD;
    float4 v0 = *(const float4*)&xr[lane*4];
    float4 v1 = *(const float4*)&xr[128 + lane*4];
    float s  = v0.x+v0.y+v0.z+v0.w + v1.x+v1.y+v1.z+v1.w;
    float ss = v0.x*v0.x+v0.y*v0.y+v0.z*v0.z+v0.w*v0.w
             + v1.x*v1.x+v1.y*v1.y+v1.z*v1.z+v1.w*v1.w;
#pragma unroll
    for (int o = 16; o; o >>= 1) {
        s  += __shfl_xor_sync(0xffffffffu, s,  o);
        ss += __shfl_xor_sync(0xffffffffu, ss, o);
    }
    float mu = s * (1.0f/256.0f);
    float var = ss * (1.0f/256.0f) - mu*mu;
    float rs = rsqrtf(var + 1e-5f);
    float* orow = g_yn + (size_t)row * DD;   // fp32 (residual path)
    int d0 = lane*4, d1 = 128 + lane*4;
    float4 gw0 = *(const float4*)&gw[d0], gw1 = *(const float4*)&gw[d1];
    float4 bw0 = *(const float4*)&bw[d0], bw1 = *(const float4*)&bw[d1];
    float4 o0, o1;
    o0.x = (v0.x-mu)*rs*gw0.x + bw0.x; o0.y = (v0.y-mu)*rs*gw0.y + bw0.y;
    o0.z = (v0.z-mu)*rs*gw0.z + bw0.z; o0.w = (v0.w-mu)*rs*gw0.w + bw0.w;
    o1.x = (v1.x-mu)*rs*gw1.x + bw1.x; o1.y = (v1.y-mu)*rs*gw1.y + bw1.y;
    o1.z = (v1.z-mu)*rs*gw1.z + bw1.z; o1.w = (v1.w-mu)*rs*gw1.w + bw1.w;
    *(float4*)&orow[d0] = o0;
    *(float4*)&orow[d1] = o1;
}

// ---------------- epilogues ----------------
// EPI 0: QKV scatter (tf32)  1: +b+res -> g_s (fp32)  2: gelu -> g_hidden (tf32)  3: +y -> out
template<int EPI>
__device__ __forceinline__ void epi_store(int gm, int gn, float v0, float v1,
                                          const float* __restrict__ biasN,
                                          const float* __restrict__ e0,
                                          float* __restrict__ outp) {
    v0 += biasN[gn]; v1 += biasN[gn+1];
    if constexpr (EPI == 0) {
        int part = gn >> 8, rem = gn & 255, h = rem >> 5, dk = rem & 31;
        int p = gm & 63, bt = gm >> 6;
        float* dst = (part == 0) ? g_q : (part == 1 ? g_k : g_v);
        *(float2*)&dst[(((size_t)bt*HH + h)*PP + p)*DKK + dk] = make_float2(f2tff(v0), f2tff(v1));
    } else if constexpr (EPI == 1) {
        int b = gm >> 15, t = (gm >> 6) & 511, p = gm & 63;
        float2 xr = *(const float2*)&e0[(((size_t)(b*PP + p))*TT + t)*DD + gn];
        *(float2*)&g_s[(size_t)gm*DD + gn] = make_float2(v0 + xr.x, v1 + xr.y);
    } else if constexpr (EPI == 2) {
        float g0 = 0.5f * v0 * (1.0f + erff(v0 * 0.70710678118654752f));
        float g1v = 0.5f * v1 * (1.0f + erff(v1 * 0.70710678118654752f));
        *(float2*)&g_hidden[(size_t)gm*FFF + gn] = make_float2(f2tff(g0), f2tff(g1v));
    } else {
        float2 y = *(const float2*)&g_yn[(size_t)gm*DD + gn];
        int b = gm >> 15, t = (gm >> 6) & 511, p = gm & 63;
        *(float2*)&outp[(((size_t)(b*PP + p))*TT + t)*DD + gn] = make_float2(y.x + v0, y.y + v1);
    }
}

// ---------------- tf32 GEMM: C[M,N] = A[M,K] * W[K,N], fused epilogue ----------------
// BM=128, BN=128, BK=32, 3-stage cp.async ring (one barrier per k-tile),
// 256 threads, warp tile 64x32 (16 MMAs/ks). Dynamic smem 107.5 KB.
#define GBM 128
#define GBN 128
#define GBK 32
#define AS_STRIDE 36    // (mod 32 = 4): A frag addr 4g+tg covers 0..31 -> conflict-free
#define BS_STRIDE 136   // (mod 32 = 8): B frag addr 8tg+g covers 0..31 -> conflict-free
#define AS_STAGE (GBM * AS_STRIDE)
#define BS_STAGE (GBK * BS_STRIDE)
#define GEMM_SMEM_BYTES ((3 * AS_STAGE + 3 * BS_STAGE) * 4)

template<int EPI>
__global__ void __launch_bounds__(256, 2) gemm_kernel(
    const float* __restrict__ biasN, const float* __restrict__ e0,
    float* __restrict__ outp, int M, int N, int K) {
    const float* A = (EPI == 0) ? g_xn : (EPI == 1) ? g_o : (EPI == 2) ? g_yn : g_hidden;
    const float* W = (EPI == 0) ? g_wq : (EPI == 1) ? g_wo : (EPI == 2) ? g_w1 : g_w2;
    extern __shared__ float smem[];
    float* As = smem;                 // [3][128][36]
    float* Bs = smem + 3 * AS_STAGE;  // [3][32][136]

    int tid = threadIdx.x;
    int bm = blockIdx.y * GBM, bn = blockIdx.x * GBN;

    auto load_stage = [&](int s, int kt) {
        float* as = As + s * AS_STAGE;
        float* bs = Bs + s * BS_STAGE;
#pragma unroll
        for (int i = 0; i < 4; i++) {       // A: 128 rows x 32 floats
            int f = tid + i * 256;
            int row = f >> 3, c4 = (f & 7) * 4;
            cpa16(smem_u32(&as[row * AS_STRIDE + c4]), A + (size_t)(bm + row) * K + kt * GBK + c4);
        }
#pragma unroll
        for (int i = 0; i < 4; i++) {       // B: 32 rows x 128 floats
            int f = tid + i * 256;
            int row = f >> 5, c4 = (f & 31) * 4;
            cpa16(smem_u32(&bs[row * BS_STRIDE + c4]), W + (size_t)(kt * GBK + row) * N + bn + c4);
        }
        asm volatile("cp.async.commit_group;");
    };

    float acc[4][4][4];
#pragma unroll
    for (int i = 0; i < 4; i++)
#pragma unroll
        for (int j = 0; j < 4; j++)
#pragma unroll
            for (int l = 0; l < 4; l++) acc[i][j][l] = 0.0f;

    int lane = tid & 31, wid = tid >> 5;
    int wm = (wid & 1) * 64, wn = (wid >> 1) * 32;
    int g = lane >> 2, tg = lane & 3;

    int nk = K / GBK;
    load_stage(0, 0);
    load_stage(1, 1);
    for (int kt = 0; kt < nk; kt++) {
        if (kt + 1 < nk) asm volatile("cp.async.wait_group 1;");
        else             asm volatile("cp.async.wait_group 0;");
        __syncthreads();
        if (kt + 2 < nk) load_stage((kt + 2) % 3, kt + 2);
        const float* as = As + (kt % 3) * AS_STAGE;
        const float* bs = Bs + (kt % 3) * BS_STAGE;
#pragma unroll
        for (int ks = 0; ks < 4; ks++) {
            int kk = ks * 8;
            uint32_t af[4][4];
#pragma unroll
            for (int mt = 0; mt < 4; mt++) {
                int r = wm + mt * 16 + g;
                float a0 = as[r * AS_STRIDE + kk + tg];
                float a1 = as[(r + 8) * AS_STRIDE + kk + tg];
                float a2 = as[r * AS_STRIDE + kk + tg + 4];
                float a3 = as[(r + 8) * AS_STRIDE + kk + tg + 4];
                if constexpr (EPI == 2) {
                    af[mt][0] = f2tf(a0); af[mt][1] = f2tf(a1);
                    af[mt][2] = f2tf(a2); af[mt][3] = f2tf(a3);
                } else {
                    af[mt][0] = __float_as_uint(a0); af[mt][1] = __float_as_uint(a1);
                    af[mt][2] = __float_as_uint(a2); af[mt][3] = __float_as_uint(a3);
                }
            }
            uint32_t bf[4][2];
#pragma unroll
            for (int nt = 0; nt < 4; nt++) {
                int c = wn + nt * 8 + g;
                bf[nt][0] = __float_as_uint(bs[(kk + tg    ) * BS_STRIDE + c]);
                bf[nt][1] = __float_as_uint(bs[(kk + tg + 4) * BS_STRIDE + c]);
            }
#pragma unroll
            for (int mt = 0; mt < 4; mt++)
#pragma unroll
                for (int nt = 0; nt < 4; nt++)
                    mma_tf32(acc[mt][nt], af[mt], bf[nt]);
        }
    }

#pragma unroll
    for (int mt = 0; mt < 4; mt++)
#pragma unroll
        for (int nt = 0; nt < 4; nt++) {
            int gn = bn + wn + nt * 8 + tg * 2;
            int r0 = bm + wm + mt * 16 + g;
            epi_store<EPI>(r0,     gn, acc[mt][nt][0], acc[mt][nt][1], biasN, e0, outp);
            epi_store<EPI>(r0 + 8, gn, acc[mt][nt][2], acc[mt][nt][3], biasN, e0, outp);
        }
}

// ---------------- attention: one CTA per (b,t,h) ----------------
__global__ void __launch_bounds__(128) attn_kernel() {
    __shared__ float Qs[64][36], Ks[64][36], Vs[64][36], Ss[64][68];
    int bth = blockIdx.x;
    int h = bth & 7, bt = bth >> 3, b = bt >> 9;
    size_t base = ((size_t)bt * HH + h) * PP * DKK;
    const float* Qg = g_q + base;
    const float* Kg = g_k + base;
    const float* Vg = g_v + base;
    int tid = threadIdx.x;
    for (int i = tid; i < 512; i += 128) {
        int r = i >> 3, c = (i & 7) * 4;
        *(float4*)&Qs[r][c] = *(const float4*)&Qg[r * 32 + c];
        *(float4*)&Ks[r][c] = *(const float4*)&Kg[r * 32 + c];
        *(float4*)&Vs[r][c] = *(const float4*)&Vg[r * 32 + c];
    }
    __syncthreads();

    int lane = tid & 31, wid = tid >> 5;
    int g = lane >> 2, tg = lane & 3;
    int mb = wid * 16;

    float acc[8][4];
#pragma unroll
    for (int i = 0; i < 8; i++)
#pragma unroll
        for (int j = 0; j < 4; j++) acc[i][j] = 0.0f;

#pragma unroll
    for (int ks = 0; ks < 4; ks++) {
        int kk = ks * 8;
        uint32_t af[4];
        af[0] = __float_as_uint(Qs[mb + g    ][kk + tg]);
        af[1] = __float_as_uint(Qs[mb + g + 8][kk + tg]);
        af[2] = __float_as_uint(Qs[mb + g    ][kk + tg + 4]);
        af[3] = __float_as_uint(Qs[mb + g + 8][kk + tg + 4]);
#pragma unroll
        for (int nt = 0; nt < 8; nt++) {
            uint32_t bf[2];
            bf[0] = __float_as_uint(Ks[nt * 8 + g][kk + tg]);
            bf[1] = __float_as_uint(Ks[nt * 8 + g][kk + tg + 4]);
            mma_tf32(acc[nt], af, bf);
        }
    }

    // softmax (fp32), bias from global (L2-resident, reused across T)
    int rA = mb + g, rB = rA + 8;
    const float* bA = g_bias + (((size_t)b * HH + h) * PP + rA) * PP;
    const float* bBr = bA + 8 * PP;
    const float sc = 0.17677669529663687f;  // 1/sqrt(32)
    float mA = -1e30f, mB = -1e30f;
#pragma unroll
    for (int nt = 0; nt < 8; nt++) {
        int c = nt * 8 + tg * 2;
        acc[nt][0] = acc[nt][0] * sc + bA[c];
        acc[nt][1] = acc[nt][1] * sc + bA[c + 1];
        acc[nt][2] = acc[nt][2] * sc + bBr[c];
        acc[nt][3] = acc[nt][3] * sc + bBr[c + 1];
        mA = fmaxf(mA, fmaxf(acc[nt][0], acc[nt][1]));
        mB = fmaxf(mB, fmaxf(acc[nt][2], acc[nt][3]));
    }
    mA = fmaxf(mA, __shfl_xor_sync(0xffffffffu, mA, 1));
    mA = fmaxf(mA, __shfl_xor_sync(0xffffffffu, mA, 2));
    mB = fmaxf(mB, __shfl_xor_sync(0xffffffffu, mB, 1));
    mB = fmaxf(mB, __shfl_xor_sync(0xffffffffu, mB, 2));
    float sA = 0.0f, sB = 0.0f;
#pragma unroll
    for (int nt = 0; nt < 8; nt++) {
        acc[nt][0] = expf(acc[nt][0] - mA);
        acc[nt][1] = expf(acc[nt][1] - mA);
        acc[nt][2] = expf(acc[nt][2] - mB);
        acc[nt][3] = expf(acc[nt][3] - mB);
        sA += acc[nt][0] + acc[nt][1];
        sB += acc[nt][2] + acc[nt][3];
    }
    sA += __shfl_xor_sync(0xffffffffu, sA, 1);
    sA += __shfl_xor_sync(0xffffffffu, sA, 2);
    sB += __shfl_xor_sync(0xffffffffu, sB, 1);
    sB += __shfl_xor_sync(0xffffffffu, sB, 2);
    float iA = 1.0f / sA, iB = 1.0f / sB;
#pragma unroll
    for (int nt = 0; nt < 8; nt++) {
        int c = nt * 8 + tg * 2;
        *(float2*)&Ss[rA][c] = make_float2(f2tff(acc[nt][0] * iA), f2tff(acc[nt][1] * iA));
        *(float2*)&Ss[rB][c] = make_float2(f2tff(acc[nt][2] * iB), f2tff(acc[nt][3] * iB));
    }
    __syncwarp();

    // O = P @ V  (warp owns its own 16 rows of Ss)
    float accO[4][4];
#pragma unroll
    for (int i = 0; i < 4; i++)
#pragma unroll
        for (int j = 0; j < 4; j++) accO[i][j] = 0.0f;
#pragma unroll
    for (int ks = 0; ks < 8; ks++) {
        int kk = ks * 8;
        uint32_t af[4];
        af[0] = __float_as_uint(Ss[mb + g    ][kk + tg]);
        af[1] = __float_as_uint(Ss[mb + g + 8][kk + tg]);
        af[2] = __float_as_uint(Ss[mb + g    ][kk + tg + 4]);
        af[3] = __float_as_uint(Ss[mb + g + 8][kk + tg + 4]);
#pragma unroll
        for (int nt = 0; nt < 4; nt++) {
            uint32_t bf[2];
            bf[0] = __float_as_uint(Vs[kk + tg    ][nt * 8 + g]);
            bf[1] = __float_as_uint(Vs[kk + tg + 4][nt * 8 + g]);
            mma_tf32(accO[nt], af, bf);
        }
    }
#pragma unroll
    for (int nt = 0; nt < 4; nt++) {
        int dk = nt * 8 + tg * 2;
        *(float2*)&g_o[((size_t)bt * PP + rA) * DD + h * 32 + dk] =
            make_float2(f2tff(accO[nt][0]), f2tff(accO[nt][1]));
        *(float2*)&g_o[((size_t)bt * PP + rB) * DD + h * 32 + dk] =
            make_float2(f2tff(accO[nt][2]), f2tff(accO[nt][3]));
    }
}

// ---------------- launch ----------------
extern "C" void kernel_launch(void* const* d_in, const int* in_sizes, int n_in,
                              void* d_out, int out_size) {
    const float* x     = (const float*)d_in[0];
    const float* pos   = (const float*)d_in[1];
    const float* w_qkv = (const float*)d_in[2];
    const float* b_qkv = (const float*)d_in[3];
    const float* w_out = (const float*)d_in[4];
    const float* b_out = (const float*)d_in[5];
    const float* w_ff1 = (const float*)d_in[6];
    const float* b_ff1 = (const float*)d_in[7];
    const float* w_ff2 = (const float*)d_in[8];
    const float* b_ff2 = (const float*)d_in[9];
    const float* w_rel = (const float*)d_in[10];
    const float* g1    = (const float*)d_in[11];
    const float* be1   = (const float*)d_in[12];
    const float* g2    = (const float*)d_in[13];
    const float* be2   = (const float*)d_in[14];
    float* out = (float*)d_out;

    // opt-in to >48KB dynamic smem (idempotent; non-stream API, capture-safe)
    cudaFuncSetAttribute(gemm_kernel<0>, cudaFuncAttributeMaxDynamicSharedMemorySize, GEMM_SMEM_BYTES);
    cudaFuncSetAttribute(gemm_kernel<1>, cudaFuncAttributeMaxDynamicSharedMemorySize, GEMM_SMEM_BYTES);
    cudaFuncSetAttribute(gemm_kernel<2>, cudaFuncAttributeMaxDynamicSharedMemorySize, GEMM_SMEM_BYTES);
    cudaFuncSetAttribute(gemm_kernel<3>, cudaFuncAttributeMaxDynamicSharedMemorySize, GEMM_SMEM_BYTES);

    cvtw_kernel<<<2048, 256>>>(w_qkv, w_out, w_ff1, w_ff2);
    relbias_kernel<<<BB * PP, 64>>>(pos, w_rel);
    ln1_kernel<<<M_TOK / 8, 256>>>(x, g1, be1);
    gemm_kernel<0><<<dim3(3 * DD / GBN, M_TOK / GBM), 256, GEMM_SMEM_BYTES>>>(b_qkv, nullptr, nullptr, M_TOK, 3 * DD, DD);
    attn_kernel<<<BB * TT * HH, 128>>>();
    gemm_kernel<1><<<dim3(DD / GBN, M_TOK / GBM), 256, GEMM_SMEM_BYTES>>>(b_out, x, nullptr, M_TOK, DD, DD);
    ln2_kernel<<<M_TOK / 8, 256>>>(g2, be2);
    gemm_kernel<2><<<dim3(FFF / GBN, M_TOK / GBM), 256, GEMM_SMEM_BYTES>>>(b_ff1, nullptr, nullptr, M_TOK, FFF, DD);
    gemm_kernel<3><<<dim3(DD / GBN, M_TOK / GBM), 256, GEMM_SMEM_BYTES>>>(b_ff2, nullptr, out, M_TOK, DD, FFF);
}

// round 11
// speedup vs baseline: 1.3853x; 1.0255x over previous
#include <cuda_runtime.h>
#include <cuda_bf16.h>
#include <cstdint>
#include <cstddef>

// Problem dims
#define BB 8
#define PP 64
#define TT 512
#define DD 256
#define HH 8
#define DKK 32
#define FFF 512
#define M_TOK (BB*TT*PP)   // 262144

// ---------------- scratch (device globals; allocation-free) ----------------
__device__ float g_xn[(size_t)M_TOK * DD];        // LN1 output (tf32-rounded), (b,t,p) rows
__device__ float g_q[(size_t)BB*TT*HH*PP*DKK];    // tf32-rounded
__device__ float g_k[(size_t)BB*TT*HH*PP*DKK];    // tf32-rounded
__device__ float g_v[(size_t)BB*TT*HH*PP*DKK];    // tf32-rounded
__device__ float g_bias[(size_t)BB*HH*PP*PP];
__device__ float g_o[(size_t)M_TOK * DD];         // attn out (tf32-rounded)
__device__ float g_s[(size_t)M_TOK * DD];         // residual pre-LN2 (fp32)
__device__ float g_yn[(size_t)M_TOK * DD];        // LN2 output (fp32: residual path)
__device__ float g_hidden[(size_t)M_TOK * FFF];   // gelu(ff1) (tf32-rounded)
// tf32-converted weights, stored TRANSPOSED: [N][K] (n-major) for ldmatrix B path
__device__ float g_wq[3*DD*DD];
__device__ float g_wo[DD*DD];
__device__ float g_w1[FFF*DD];
__device__ float g_w2[DD*FFF];

// ---------------- small helpers ----------------
__device__ __forceinline__ uint32_t f2tf(float f) {
    uint32_t r; asm("cvt.rna.tf32.f32 %0, %1;" : "=r"(r) : "f"(f)); return r;
}
__device__ __forceinline__ float f2tff(float f) {
    uint32_t r = f2tf(f); return __uint_as_float(r);
}
__device__ __forceinline__ void mma_tf32(float* c, const uint32_t* a, const uint32_t* b) {
    asm volatile(
        "mma.sync.aligned.m16n8k8.row.col.f32.tf32.tf32.f32 "
        "{%0,%1,%2,%3},{%4,%5,%6,%7},{%8,%9},{%0,%1,%2,%3};"
        : "+f"(c[0]), "+f"(c[1]), "+f"(c[2]), "+f"(c[3])
        : "r"(a[0]), "r"(a[1]), "r"(a[2]), "r"(a[3]), "r"(b[0]), "r"(b[1]));
}
__device__ __forceinline__ uint32_t smem_u32(const void* p) {
    return (uint32_t)__cvta_generic_to_shared(p);
}
__device__ __forceinline__ void cpa16(uint32_t s, const void* g) {
    asm volatile("cp.async.cg.shared.global [%0], [%1], 16;" :: "r"(s), "l"(g));
}
__device__ __forceinline__ void ldsm4(uint32_t* r, uint32_t a) {
    asm volatile("ldmatrix.sync.aligned.m8n8.x4.shared.b16 {%0,%1,%2,%3}, [%4];"
        : "=r"(r[0]), "=r"(r[1]), "=r"(r[2]), "=r"(r[3]) : "r"(a));
}

// ---------------- weight tf32 pre-conversion + transpose to [N][K] ----------------
__global__ void cvtw_t(const float* __restrict__ src, float* __restrict__ dst, int K, int N) {
    __shared__ float t[32][33];
    int k0 = blockIdx.x * 32, n0 = blockIdx.y * 32;
    int tx = threadIdx.x, ty = threadIdx.y;   // 32 x 8
#pragma unroll
    for (int i = 0; i < 32; i += 8)
        t[ty + i][tx] = src[(size_t)(k0 + ty + i) * N + n0 + tx];
    __syncthreads();
#pragma unroll
    for (int i = 0; i < 32; i += 8)
        dst[(size_t)(n0 + ty + i) * K + k0 + tx] = f2tff(t[tx][ty + i]);
}

// ---------------- rel-pos bias ----------------
__global__ void relbias_kernel(const float* __restrict__ pos, const float* __restrict__ w_rel) {
    int bp = blockIdx.x;
    int b = bp >> 6, p = bp & 63, q = threadIdx.x;
    const float D2R = 0.017453292519943295f;
    float latp = pos[(size_t)bp*2] * D2R, lonp = pos[(size_t)bp*2+1] * D2R;
    int bq = (b << 6) | q;
    float latq = pos[(size_t)bq*2] * D2R, lonq = pos[(size_t)bq*2+1] * D2R;
    float dlat = latp - latq, dlon = lonp - lonq;
    float dx = dlon * cosf((latp + latq) * 0.5f);
    float dy = dlat;
    float sdlat = sinf(dlat * 0.5f), sdlon = sinf(dlon * 0.5f);
    float a = sdlat*sdlat + cosf(latp)*cosf(latq)*sdlon*sdlon;
    float sq = sqrtf(fmaxf(a, 1e-12f));
    sq = fminf(fmaxf(sq, 0.0f), 1.0f - 1e-7f);
    float dist = 2.0f * 6371.0f * asinf(sq);
    float bear = atan2f(sinf(dlon)*cosf(latq),
                        cosf(latp)*sinf(latq) - sinf(latp)*cosf(latq)*cosf(dlon));
    float r0 = dx, r1 = dy, r2 = dist * (1.0f/500.0f), r3 = sinf(bear);
#pragma unroll
    for (int hh = 0; hh < HH; hh++) {
        float v = r0*w_rel[hh] + r1*w_rel[HH+hh] + r2*w_rel[2*HH+hh] + r3*w_rel[3*HH+hh];
        g_bias[(((size_t)b*HH + hh)*PP + p)*PP + q] = v;
    }
}

// ---------------- LayerNorm kernels (warp per 256-wide row) ----------------
__global__ void __launch_bounds__(256) ln1_kernel(const float* __restrict__ x,
                                                  const float* __restrict__ gw,
                                                  const float* __restrict__ bw) {
    int row = blockIdx.x * 8 + (threadIdx.x >> 5);   // (b,p,t) order
    int lane = threadIdx.x & 31;
    const float* xr = x + (size_t)row * DD;
    float4 v0 = *(const float4*)&xr[lane*4];
    float4 v1 = *(const float4*)&xr[128 + lane*4];
    float s  = v0.x+v0.y+v0.z+v0.w + v1.x+v1.y+v1.z+v1.w;
    float ss = v0.x*v0.x+v0.y*v0.y+v0.z*v0.z+v0.w*v0.w
             + v1.x*v1.x+v1.y*v1.y+v1.z*v1.z+v1.w*v1.w;
#pragma unroll
    for (int o = 16; o; o >>= 1) {
        s  += __shfl_xor_sync(0xffffffffu, s,  o);
        ss += __shfl_xor_sync(0xffffffffu, ss, o);
    }
    float mu = s * (1.0f/256.0f);
    float var = ss * (1.0f/256.0f) - mu*mu;
    float rs = rsqrtf(var + 1e-5f);
    int b = row >> 15, p = (row >> 9) & 63, t = row & 511;
    float* orow = g_xn + (((size_t)(b*TT + t))*PP + p) * DD;
    int d0 = lane*4, d1 = 128 + lane*4;
    float4 gw0 = *(const float4*)&gw[d0], gw1 = *(const float4*)&gw[d1];
    float4 bw0 = *(const float4*)&bw[d0], bw1 = *(const float4*)&bw[d1];
    float4 o0, o1;
    o0.x = f2tff((v0.x-mu)*rs*gw0.x + bw0.x); o0.y = f2tff((v0.y-mu)*rs*gw0.y + bw0.y);
    o0.z = f2tff((v0.z-mu)*rs*gw0.z + bw0.z); o0.w = f2tff((v0.w-mu)*rs*gw0.w + bw0.w);
    o1.x = f2tff((v1.x-mu)*rs*gw1.x + bw1.x); o1.y = f2tff((v1.y-mu)*rs*gw1.y + bw1.y);
    o1.z = f2tff((v1.z-mu)*rs*gw1.z + bw1.z); o1.w = f2tff((v1.w-mu)*rs*gw1.w + bw1.w);
    *(float4*)&orow[d0] = o0;
    *(float4*)&orow[d1] = o1;
}

__global__ void __launch_bounds__(256) ln2_kernel(const float* __restrict__ gw,
                                                  const float* __restrict__ bw) {
    int row = blockIdx.x * 8 + (threadIdx.x >> 5);
    int lane = threadIdx.x & 31;
    const float* xr = g_s + (size_t)row * DD;
    float4 v0 = *(const float4*)&xr[lane*4];
    float4 v1 = *(const float4*)&xr[128 + lane*4];
    float s  = v0.x+v0.y+v0.z+v0.w + v1.x+v1.y+v1.z+v1.w;
    float ss = v0.x*v0.x+v0.y*v0.y+v0.z*v0.z+v0.w*v0.w
             + v1.x*v1.x+v1.y*v1.y+v1.z*v1.z+v1.w*v1.w;
#pragma unroll
    for (int o = 16; o; o >>= 1) {
        s  += __shfl_xor_sync(0xffffffffu, s,  o);
        ss += __shfl_xor_sync(0xffffffffu, ss, o);
    }
    float mu = s * (1.0f/256.0f);
    float var = ss * (1.0f/256.0f) - mu*mu;
    float rs = rsqrtf(var + 1e-5f);
    float* orow = g_yn + (size_t)row * DD;   // fp32 (residual path)
    int d0 = lane*4, d1 = 128 + lane*4;
    float4 gw0 = *(const float4*)&gw[d0], gw1 = *(const float4*)&gw[d1];
    float4 bw0 = *(const float4*)&bw[d0], bw1 = *(const float4*)&bw[d1];
    float4 o0, o1;
    o0.x = (v0.x-mu)*rs*gw0.x + bw0.x; o0.y = (v0.y-mu)*rs*gw0.y + bw0.y;
    o0.z = (v0.z-mu)*rs*gw0.z + bw0.z; o0.w = (v0.w-mu)*rs*gw0.w + bw0.w;
    o1.x = (v1.x-mu)*rs*gw1.x + bw1.x; o1.y = (v1.y-mu)*rs*gw1.y + bw1.y;
    o1.z = (v1.z-mu)*rs*gw1.z + bw1.z; o1.w = (v1.w-mu)*rs*gw1.w + bw1.w;
    *(float4*)&orow[d0] = o0;
    *(float4*)&orow[d1] = o1;
}

// ---------------- epilogues ----------------
// EPI 0: QKV scatter (tf32)  1: +b+res -> g_s (fp32)  2: gelu -> g_hidden (tf32)  3: +y -> out
template<int EPI>
__device__ __forceinline__ void epi_store(int gm, int gn, float v0, float v1,
                                          const float* __restrict__ biasN,
                                          const float* __restrict__ e0,
                                          float* __restrict__ outp) {
    v0 += biasN[gn]; v1 += biasN[gn+1];
    if constexpr (EPI == 0) {
        int part = gn >> 8, rem = gn & 255, h = rem >> 5, dk = rem & 31;
        int p = gm & 63, bt = gm >> 6;
        float* dst = (part == 0) ? g_q : (part == 1 ? g_k : g_v);
        *(float2*)&dst[(((size_t)bt*HH + h)*PP + p)*DKK + dk] = make_float2(f2tff(v0), f2tff(v1));
    } else if constexpr (EPI == 1) {
        int b = gm >> 15, t = (gm >> 6) & 511, p = gm & 63;
        float2 xr = *(const float2*)&e0[(((size_t)(b*PP + p))*TT + t)*DD + gn];
        *(float2*)&g_s[(size_t)gm*DD + gn] = make_float2(v0 + xr.x, v1 + xr.y);
    } else if constexpr (EPI == 2) {
        float g0 = 0.5f * v0 * (1.0f + erff(v0 * 0.70710678118654752f));
        float g1v = 0.5f * v1 * (1.0f + erff(v1 * 0.70710678118654752f));
        *(float2*)&g_hidden[(size_t)gm*FFF + gn] = make_float2(f2tff(g0), f2tff(g1v));
    } else {
        float2 y = *(const float2*)&g_yn[(size_t)gm*DD + gn];
        int b = gm >> 15, t = (gm >> 6) & 511, p = gm & 63;
        *(float2*)&outp[(((size_t)(b*PP + p))*TT + t)*DD + gn] = make_float2(y.x + v0, y.y + v1);
    }
}

// ---------------- tf32 GEMM: C[M,N] = A[M,K] * W^T[N,K], fused epilogue ----------------
// BM=128, BN=128, BK=32, 3-stage cp.async ring, 256 threads, warp tile 64x32.
// Both operands n/m-major [rows][32k] in smem; fragments via ldmatrix.x4.
#define GBM 128
#define GBN 128
#define GBK 32
#define TS_STRIDE 36    // 144B row stride: ldmatrix 8-row pieces conflict-free
#define TS_STAGE (128 * TS_STRIDE)
#define GEMM_SMEM_BYTES ((6 * TS_STAGE) * 4)

template<int EPI>
__global__ void __launch_bounds__(256, 2) gemm_kernel(
    const float* __restrict__ biasN, const float* __restrict__ e0,
    float* __restrict__ outp, int M, int N, int K) {
    const float* A = (EPI == 0) ? g_xn : (EPI == 1) ? g_o : (EPI == 2) ? g_yn : g_hidden;
    const float* W = (EPI == 0) ? g_wq : (EPI == 1) ? g_wo : (EPI == 2) ? g_w1 : g_w2;  // [N][K]
    extern __shared__ float smem[];
    float* As = smem;                 // [3][128][36]  rows = m
    float* Bs = smem + 3 * TS_STAGE;  // [3][128][36]  rows = n

    int tid = threadIdx.x;
    int bm = blockIdx.y * GBM, bn = blockIdx.x * GBN;

    auto load_stage = [&](int s, int kt) {
        float* as = As + s * TS_STAGE;
        float* bs = Bs + s * TS_STAGE;
#pragma unroll
        for (int i = 0; i < 4; i++) {       // A: 128 rows x 32 floats
            int f = tid + i * 256;
            int row = f >> 3, c4 = (f & 7) * 4;
            cpa16(smem_u32(&as[row * TS_STRIDE + c4]), A + (size_t)(bm + row) * K + kt * GBK + c4);
        }
#pragma unroll
        for (int i = 0; i < 4; i++) {       // B: 128 n-rows x 32 floats (W is [N][K])
            int f = tid + i * 256;
            int row = f >> 3, c4 = (f & 7) * 4;
            cpa16(smem_u32(&bs[row * TS_STRIDE + c4]), W + (size_t)(bn + row) * K + kt * GBK + c4);
        }
        asm volatile("cp.async.commit_group;");
    };

    float acc[4][4][4];
#pragma unroll
    for (int i = 0; i < 4; i++)
#pragma unroll
        for (int j = 0; j < 4; j++)
#pragma unroll
            for (int l = 0; l < 4; l++) acc[i][j][l] = 0.0f;

    int lane = tid & 31, wid = tid >> 5;
    int wm = (wid & 1) * 64, wn = (wid >> 1) * 32;
    int g = lane >> 2, tg = lane & 3;
    int lrow = lane & 7, lpi = lane >> 3;
    // ldmatrix per-lane addressing (float offsets within a stage)
    int rowA = wm + lrow + (lpi & 1) * 8;   int colA = (lpi >> 1) * 4;
    int rowB = wn + lrow + (lpi >> 1) * 8;  int colB = (lpi & 1) * 4;

    int nk = K / GBK;
    load_stage(0, 0);
    load_stage(1, 1);
    for (int kt = 0; kt < nk; kt++) {
        if (kt + 1 < nk) asm volatile("cp.async.wait_group 1;");
        else             asm volatile("cp.async.wait_group 0;");
        __syncthreads();
        if (kt + 2 < nk) load_stage((kt + 2) % 3, kt + 2);
        uint32_t a_st = smem_u32(As + (kt % 3) * TS_STAGE);
        uint32_t b_st = smem_u32(Bs + (kt % 3) * TS_STAGE);
#pragma unroll
        for (int ks = 0; ks < 4; ks++) {
            int kk = ks * 8;
            uint32_t af[4][4];
#pragma unroll
            for (int mt = 0; mt < 4; mt++) {
                ldsm4(af[mt], a_st + (uint32_t)(((rowA + mt * 16) * TS_STRIDE) + kk + colA) * 4);
                if constexpr (EPI == 2) {
                    af[mt][0] = f2tf(__uint_as_float(af[mt][0]));
                    af[mt][1] = f2tf(__uint_as_float(af[mt][1]));
                    af[mt][2] = f2tf(__uint_as_float(af[mt][2]));
                    af[mt][3] = f2tf(__uint_as_float(af[mt][3]));
                }
            }
            uint32_t bf[4][2];
#pragma unroll
            for (int p = 0; p < 2; p++) {
                uint32_t br[4];
                ldsm4(br, b_st + (uint32_t)(((rowB + p * 16) * TS_STRIDE) + kk + colB) * 4);
                bf[2*p][0] = br[0]; bf[2*p][1] = br[1];
                bf[2*p+1][0] = br[2]; bf[2*p+1][1] = br[3];
            }
#pragma unroll
            for (int mt = 0; mt < 4; mt++)
#pragma unroll
                for (int nt = 0; nt < 4; nt++)
                    mma_tf32(acc[mt][nt], af[mt], bf[nt]);
        }
    }

#pragma unroll
    for (int mt = 0; mt < 4; mt++)
#pragma unroll
        for (int nt = 0; nt < 4; nt++) {
            int gn = bn + wn + nt * 8 + tg * 2;
            int r0 = bm + wm + mt * 16 + g;
            epi_store<EPI>(r0,     gn, acc[mt][nt][0], acc[mt][nt][1], biasN, e0, outp);
            epi_store<EPI>(r0 + 8, gn, acc[mt][nt][2], acc[mt][nt][3], biasN, e0, outp);
        }
}

// ---------------- attention: one CTA per (b,t,h), Ss aliases Q|K ----------------
__global__ void __launch_bounds__(128) attn_kernel() {
    __shared__ float sbuf[2 * 64 * 36];   // Qs | Ks, later reused as Ss[64][68]
    __shared__ float Vs[64][40];
    float (*Qs)[36] = (float(*)[36])sbuf;
    float (*Ks)[36] = (float(*)[36])(sbuf + 64 * 36);
    float (*Ss)[68] = (float(*)[68])sbuf;

    int bth = blockIdx.x;
    int h = bth & 7, bt = bth >> 3, b = bt >> 9;
    size_t base = ((size_t)bt * HH + h) * PP * DKK;
    const float* Qg = g_q + base;
    const float* Kg = g_k + base;
    const float* Vg = g_v + base;
    int tid = threadIdx.x;
    for (int i = tid; i < 512; i += 128) {
        int r = i >> 3, c = (i & 7) * 4;
        *(float4*)&Qs[r][c] = *(const float4*)&Qg[r * 32 + c];
        *(float4*)&Ks[r][c] = *(const float4*)&Kg[r * 32 + c];
        *(float4*)&Vs[r][c] = *(const float4*)&Vg[r * 32 + c];
    }
    __syncthreads();

    int lane = tid & 31, wid = tid >> 5;
    int g = lane >> 2, tg = lane & 3;
    int mb = wid * 16;

    float acc[8][4];
#pragma unroll
    for (int i = 0; i < 8; i++)
#pragma unroll
        for (int j = 0; j < 4; j++) acc[i][j] = 0.0f;

#pragma unroll
    for (int ks = 0; ks < 4; ks++) {
        int kk = ks * 8;
        uint32_t af[4];
        af[0] = __float_as_uint(Qs[mb + g    ][kk + tg]);
        af[1] = __float_as_uint(Qs[mb + g + 8][kk + tg]);
        af[2] = __float_as_uint(Qs[mb + g    ][kk + tg + 4]);
        af[3] = __float_as_uint(Qs[mb + g + 8][kk + tg + 4]);
#pragma unroll
        for (int nt = 0; nt < 8; nt++) {
            uint32_t bf[2];
            bf[0] = __float_as_uint(Ks[nt * 8 + g][kk + tg]);
            bf[1] = __float_as_uint(Ks[nt * 8 + g][kk + tg + 4]);
            mma_tf32(acc[nt], af, bf);
        }
    }

    // softmax (fp32), bias from global (L2-resident, reused across T)
    int rA = mb + g, rB = rA + 8;
    const float* bA = g_bias + (((size_t)b * HH + h) * PP + rA) * PP;
    const float* bBr = bA + 8 * PP;
    const float sc = 0.17677669529663687f;  // 1/sqrt(32)
    float mA = -1e30f, mB = -1e30f;
#pragma unroll
    for (int nt = 0; nt < 8; nt++) {
        int c = nt * 8 + tg * 2;
        acc[nt][0] = acc[nt][0] * sc + bA[c];
        acc[nt][1] = acc[nt][1] * sc + bA[c + 1];
        acc[nt][2] = acc[nt][2] * sc + bBr[c];
        acc[nt][3] = acc[nt][3] * sc + bBr[c + 1];
        mA = fmaxf(mA, fmaxf(acc[nt][0], acc[nt][1]));
        mB = fmaxf(mB, fmaxf(acc[nt][2], acc[nt][3]));
    }
    mA = fmaxf(mA, __shfl_xor_sync(0xffffffffu, mA, 1));
    mA = fmaxf(mA, __shfl_xor_sync(0xffffffffu, mA, 2));
    mB = fmaxf(mB, __shfl_xor_sync(0xffffffffu, mB, 1));
    mB = fmaxf(mB, __shfl_xor_sync(0xffffffffu, mB, 2));
    float sA = 0.0f, sB = 0.0f;
#pragma unroll
    for (int nt = 0; nt < 8; nt++) {
        acc[nt][0] = expf(acc[nt][0] - mA);
        acc[nt][1] = expf(acc[nt][1] - mA);
        acc[nt][2] = expf(acc[nt][2] - mB);
        acc[nt][3] = expf(acc[nt][3] - mB);
        sA += acc[nt][0] + acc[nt][1];
        sB += acc[nt][2] + acc[nt][3];
    }
    sA += __shfl_xor_sync(0xffffffffu, sA, 1);
    sA += __shfl_xor_sync(0xffffffffu, sA, 2);
    sB += __shfl_xor_sync(0xffffffffu, sB, 1);
    sB += __shfl_xor_sync(0xffffffffu, sB, 2);
    float iA = 1.0f / sA, iB = 1.0f / sB;

    // all warps done reading Qs/Ks before Ss overwrites the same memory
    __syncthreads();
#pragma unroll
    for (int nt = 0; nt < 8; nt++) {
        int c = nt * 8 + tg * 2;
        *(float2*)&Ss[rA][c] = make_float2(f2tff(acc[nt][0] * iA), f2tff(acc[nt][1] * iA));
        *(float2*)&Ss[rB][c] = make_float2(f2tff(acc[nt][2] * iB), f2tff(acc[nt][3] * iB));
    }
    __syncwarp();

    // O = P @ V  (warp owns its own 16 rows of Ss)
    float accO[4][4];
#pragma unroll
    for (int i = 0; i < 4; i++)
#pragma unroll
        for (int j = 0; j < 4; j++) accO[i][j] = 0.0f;
#pragma unroll
    for (int ks = 0; ks < 8; ks++) {
        int kk = ks * 8;
        uint32_t af[4];
        af[0] = __float_as_uint(Ss[mb + g    ][kk + tg]);
        af[1] = __float_as_uint(Ss[mb + g + 8][kk + tg]);
        af[2] = __float_as_uint(Ss[mb + g    ][kk + tg + 4]);
        af[3] = __float_as_uint(Ss[mb + g + 8][kk + tg + 4]);
#pragma unroll
        for (int nt = 0; nt < 4; nt++) {
            uint32_t bf[2];
            bf[0] = __float_as_uint(Vs[kk + tg    ][nt * 8 + g]);
            bf[1] = __float_as_uint(Vs[kk + tg + 4][nt * 8 + g]);
            mma_tf32(accO[nt], af, bf);
        }
    }
#pragma unroll
    for (int nt = 0; nt < 4; nt++) {
        int dk = nt * 8 + tg * 2;
        *(float2*)&g_o[((size_t)bt * PP + rA) * DD + h * 32 + dk] =
            make_float2(f2tff(accO[nt][0]), f2tff(accO[nt][1]));
        *(float2*)&g_o[((size_t)bt * PP + rB) * DD + h * 32 + dk] =
            make_float2(f2tff(accO[nt][2]), f2tff(accO[nt][3]));
    }
}

// ---------------- launch ----------------
extern "C" void kernel_launch(void* const* d_in, const int* in_sizes, int n_in,
                              void* d_out, int out_size) {
    const float* x     = (const float*)d_in[0];
    const float* pos   = (const float*)d_in[1];
    const float* w_qkv = (const float*)d_in[2];
    const float* b_qkv = (const float*)d_in[3];
    const float* w_out = (const float*)d_in[4];
    const float* b_out = (const float*)d_in[5];
    const float* w_ff1 = (const float*)d_in[6];
    const float* b_ff1 = (const float*)d_in[7];
    const float* w_ff2 = (const float*)d_in[8];
    const float* b_ff2 = (const float*)d_in[9];
    const float* w_rel = (const float*)d_in[10];
    const float* g1    = (const float*)d_in[11];
    const float* be1   = (const float*)d_in[12];
    const float* g2    = (const float*)d_in[13];
    const float* be2   = (const float*)d_in[14];
    float* out = (float*)d_out;

    // opt-in to >48KB dynamic smem (idempotent; non-stream API, capture-safe)
    cudaFuncSetAttribute(gemm_kernel<0>, cudaFuncAttributeMaxDynamicSharedMemorySize, GEMM_SMEM_BYTES);
    cudaFuncSetAttribute(gemm_kernel<1>, cudaFuncAttributeMaxDynamicSharedMemorySize, GEMM_SMEM_BYTES);
    cudaFuncSetAttribute(gemm_kernel<2>, cudaFuncAttributeMaxDynamicSharedMemorySize, GEMM_SMEM_BYTES);
    cudaFuncSetAttribute(gemm_kernel<3>, cudaFuncAttributeMaxDynamicSharedMemorySize, GEMM_SMEM_BYTES);

    float *p_wq, *p_wo, *p_w1, *p_w2;
    cudaGetSymbolAddress((void**)&p_wq, g_wq);
    cudaGetSymbolAddress((void**)&p_wo, g_wo);
    cudaGetSymbolAddress((void**)&p_w1, g_w1);
    cudaGetSymbolAddress((void**)&p_w2, g_w2);

    // transpose + tf32-round weights: dst[n][k] = tf32(src[k][n])
    cvtw_t<<<dim3(DD/32, 3*DD/32), dim3(32, 8)>>>(w_qkv, p_wq, DD, 3*DD);
    cvtw_t<<<dim3(DD/32, DD/32),   dim3(32, 8)>>>(w_out, p_wo, DD, DD);
    cvtw_t<<<dim3(DD/32, FFF/32),  dim3(32, 8)>>>(w_ff1, p_w1, DD, FFF);
    cvtw_t<<<dim3(FFF/32, DD/32),  dim3(32, 8)>>>(w_ff2, p_w2, FFF, DD);

    relbias_kernel<<<BB * PP, 64>>>(pos, w_rel);
    ln1_kernel<<<M_TOK / 8, 256>>>(x, g1, be1);
    gemm_kernel<0><<<dim3(3 * DD / GBN, M_TOK / GBM), 256, GEMM_SMEM_BYTES>>>(b_qkv, nullptr, nullptr, M_TOK, 3 * DD, DD);
    attn_kernel<<<BB * TT * HH, 128>>>();
    gemm_kernel<1><<<dim3(DD / GBN, M_TOK / GBM), 256, GEMM_SMEM_BYTES>>>(b_out, x, nullptr, M_TOK, DD, DD);
    ln2_kernel<<<M_TOK / 8, 256>>>(g2, be2);
    gemm_kernel<2><<<dim3(FFF / GBN, M_TOK / GBM), 256, GEMM_SMEM_BYTES>>>(b_ff1, nullptr, nullptr, M_TOK, FFF, DD);
    gemm_kernel<3><<<dim3(DD / GBN, M_TOK / GBM), 256, GEMM_SMEM_BYTES>>>(b_ff2, nullptr, out, M_TOK, DD, FFF);
}

// round 12
// speedup vs baseline: 2.0407x; 1.4732x over previous
#include <cuda_runtime.h>
#include <cuda_fp16.h>
#include <cstdint>
#include <cstddef>

// Problem dims
#define BB 8
#define PP 64
#define TT 512
#define DD 256
#define HH 8
#define DKK 32
#define FFF 512
#define M_TOK (BB*TT*PP)   // 262144

// ---------------- scratch (device globals; allocation-free) ----------------
__device__ __half g_xn[(size_t)M_TOK * DD];       // LN1 output (fp16), (b,t,p) rows
__device__ __half g_q[(size_t)BB*TT*HH*PP*DKK];
__device__ __half g_k[(size_t)BB*TT*HH*PP*DKK];
__device__ __half g_v[(size_t)BB*TT*HH*PP*DKK];
__device__ float  g_bias[(size_t)BB*HH*PP*PP];
__device__ __half g_o[(size_t)M_TOK * DD];        // attn out (fp16)
__device__ float  g_s[(size_t)M_TOK * DD];        // residual pre-LN2 (fp32)
__device__ float  g_yn[(size_t)M_TOK * DD];       // LN2 output fp32 (residual path)
__device__ __half g_ynh[(size_t)M_TOK * DD];      // LN2 output fp16 (FF1 operand)
__device__ __half g_hidden[(size_t)M_TOK * FFF];  // gelu(ff1) fp16
// fp16 weights, TRANSPOSED: [N][K]
__device__ __half g_wq[3*DD*DD];
__device__ __half g_wo[DD*DD];
__device__ __half g_w1[FFF*DD];
__device__ __half g_w2[DD*FFF];

// ---------------- small helpers ----------------
__device__ __forceinline__ void mma_f16(float* c, const uint32_t* a, const uint32_t* b) {
    asm volatile(
        "mma.sync.aligned.m16n8k16.row.col.f32.f16.f16.f32 "
        "{%0,%1,%2,%3},{%4,%5,%6,%7},{%8,%9},{%0,%1,%2,%3};"
        : "+f"(c[0]), "+f"(c[1]), "+f"(c[2]), "+f"(c[3])
        : "r"(a[0]), "r"(a[1]), "r"(a[2]), "r"(a[3]), "r"(b[0]), "r"(b[1]));
}
__device__ __forceinline__ uint32_t smem_u32(const void* p) {
    return (uint32_t)__cvta_generic_to_shared(p);
}
__device__ __forceinline__ void cpa16(uint32_t s, const void* g) {
    asm volatile("cp.async.cg.shared.global [%0], [%1], 16;" :: "r"(s), "l"(g));
}
__device__ __forceinline__ void ldsm4(uint32_t* r, uint32_t a) {
    asm volatile("ldmatrix.sync.aligned.m8n8.x4.shared.b16 {%0,%1,%2,%3}, [%4];"
        : "=r"(r[0]), "=r"(r[1]), "=r"(r[2]), "=r"(r[3]) : "r"(a));
}
__device__ __forceinline__ void ldsm4t(uint32_t* r, uint32_t a) {
    asm volatile("ldmatrix.sync.aligned.m8n8.x4.trans.shared.b16 {%0,%1,%2,%3}, [%4];"
        : "=r"(r[0]), "=r"(r[1]), "=r"(r[2]), "=r"(r[3]) : "r"(a));
}

// ---------------- weight fp16 conversion + transpose to [N][K] ----------------
__global__ void cvtw_t(const float* __restrict__ src, __half* __restrict__ dst, int K, int N) {
    __shared__ float t[32][33];
    int k0 = blockIdx.x * 32, n0 = blockIdx.y * 32;
    int tx = threadIdx.x, ty = threadIdx.y;   // 32 x 8
#pragma unroll
    for (int i = 0; i < 32; i += 8)
        t[ty + i][tx] = src[(size_t)(k0 + ty + i) * N + n0 + tx];
    __syncthreads();
#pragma unroll
    for (int i = 0; i < 32; i += 8)
        dst[(size_t)(n0 + ty + i) * K + k0 + tx] = __float2half_rn(t[tx][ty + i]);
}

// ---------------- rel-pos bias ----------------
__global__ void relbias_kernel(const float* __restrict__ pos, const float* __restrict__ w_rel) {
    int bp = blockIdx.x;
    int b = bp >> 6, p = bp & 63, q = threadIdx.x;
    const float D2R = 0.017453292519943295f;
    float latp = pos[(size_t)bp*2] * D2R, lonp = pos[(size_t)bp*2+1] * D2R;
    int bq = (b << 6) | q;
    float latq = pos[(size_t)bq*2] * D2R, lonq = pos[(size_t)bq*2+1] * D2R;
    float dlat = latp - latq, dlon = lonp - lonq;
    float dx = dlon * cosf((latp + latq) * 0.5f);
    float dy = dlat;
    float sdlat = sinf(dlat * 0.5f), sdlon = sinf(dlon * 0.5f);
    float a = sdlat*sdlat + cosf(latp)*cosf(latq)*sdlon*sdlon;
    float sq = sqrtf(fmaxf(a, 1e-12f));
    sq = fminf(fmaxf(sq, 0.0f), 1.0f - 1e-7f);
    float dist = 2.0f * 6371.0f * asinf(sq);
    float bear = atan2f(sinf(dlon)*cosf(latq),
                        cosf(latp)*sinf(latq) - sinf(latp)*cosf(latq)*cosf(dlon));
    float r0 = dx, r1 = dy, r2 = dist * (1.0f/500.0f), r3 = sinf(bear);
#pragma unroll
    for (int hh = 0; hh < HH; hh++) {
        float v = r0*w_rel[hh] + r1*w_rel[HH+hh] + r2*w_rel[2*HH+hh] + r3*w_rel[3*HH+hh];
        g_bias[(((size_t)b*HH + hh)*PP + p)*PP + q] = v;
    }
}

// ---------------- LayerNorm kernels (warp per 256-wide row) ----------------
__global__ void __launch_bounds__(256) ln1_kernel(const float* __restrict__ x,
                                                  const float* __restrict__ gw,
                                                  const float* __restrict__ bw) {
    int row = blockIdx.x * 8 + (threadIdx.x >> 5);   // (b,p,t) order
    int lane = threadIdx.x & 31;
    const float* xr = x + (size_t)row * DD;
    float4 v0 = *(const float4*)&xr[lane*4];
    float4 v1 = *(const float4*)&xr[128 + lane*4];
    float s  = v0.x+v0.y+v0.z+v0.w + v1.x+v1.y+v1.z+v1.w;
    float ss = v0.x*v0.x+v0.y*v0.y+v0.z*v0.z+v0.w*v0.w
             + v1.x*v1.x+v1.y*v1.y+v1.z*v1.z+v1.w*v1.w;
#pragma unroll
    for (int o = 16; o; o >>= 1) {
        s  += __shfl_xor_sync(0xffffffffu, s,  o);
        ss += __shfl_xor_sync(0xffffffffu, ss, o);
    }
    float mu = s * (1.0f/256.0f);
    float var = ss * (1.0f/256.0f) - mu*mu;
    float rs = rsqrtf(var + 1e-5f);
    int b = row >> 15, p = (row >> 9) & 63, t = row & 511;
    __half* orow = g_xn + (((size_t)(b*TT + t))*PP + p) * DD;
    int d0 = lane*4, d1 = 128 + lane*4;
    float4 gw0 = *(const float4*)&gw[d0], gw1 = *(const float4*)&gw[d1];
    float4 bw0 = *(const float4*)&bw[d0], bw1 = *(const float4*)&bw[d1];
    half2 h00 = __floats2half2_rn((v0.x-mu)*rs*gw0.x + bw0.x, (v0.y-mu)*rs*gw0.y + bw0.y);
    half2 h01 = __floats2half2_rn((v0.z-mu)*rs*gw0.z + bw0.z, (v0.w-mu)*rs*gw0.w + bw0.w);
    half2 h10 = __floats2half2_rn((v1.x-mu)*rs*gw1.x + bw1.x, (v1.y-mu)*rs*gw1.y + bw1.y);
    half2 h11 = __floats2half2_rn((v1.z-mu)*rs*gw1.z + bw1.z, (v1.w-mu)*rs*gw1.w + bw1.w);
    *(half2*)&orow[d0] = h00; *(half2*)&orow[d0+2] = h01;
    *(half2*)&orow[d1] = h10; *(half2*)&orow[d1+2] = h11;
}

__global__ void __launch_bounds__(256) ln2_kernel(const float* __restrict__ gw,
                                                  const float* __restrict__ bw) {
    int row = blockIdx.x * 8 + (threadIdx.x >> 5);
    int lane = threadIdx.x & 31;
    const float* xr = g_s + (size_t)row * DD;
    float4 v0 = *(const float4*)&xr[lane*4];
    float4 v1 = *(const float4*)&xr[128 + lane*4];
    float s  = v0.x+v0.y+v0.z+v0.w + v1.x+v1.y+v1.z+v1.w;
    float ss = v0.x*v0.x+v0.y*v0.y+v0.z*v0.z+v0.w*v0.w
             + v1.x*v1.x+v1.y*v1.y+v1.z*v1.z+v1.w*v1.w;
#pragma unroll
    for (int o = 16; o; o >>= 1) {
        s  += __shfl_xor_sync(0xffffffffu, s,  o);
        ss += __shfl_xor_sync(0xffffffffu, ss, o);
    }
    float mu = s * (1.0f/256.0f);
    float var = ss * (1.0f/256.0f) - mu*mu;
    float rs = rsqrtf(var + 1e-5f);
    float* orow = g_yn + (size_t)row * DD;     // fp32 (residual path)
    __half* ohrow = g_ynh + (size_t)row * DD;  // fp16 (FF1 operand)
    int d0 = lane*4, d1 = 128 + lane*4;
    float4 gw0 = *(const float4*)&gw[d0], gw1 = *(const float4*)&gw[d1];
    float4 bw0 = *(const float4*)&bw[d0], bw1 = *(const float4*)&bw[d1];
    float4 o0, o1;
    o0.x = (v0.x-mu)*rs*gw0.x + bw0.x; o0.y = (v0.y-mu)*rs*gw0.y + bw0.y;
    o0.z = (v0.z-mu)*rs*gw0.z + bw0.z; o0.w = (v0.w-mu)*rs*gw0.w + bw0.w;
    o1.x = (v1.x-mu)*rs*gw1.x + bw1.x; o1.y = (v1.y-mu)*rs*gw1.y + bw1.y;
    o1.z = (v1.z-mu)*rs*gw1.z + bw1.z; o1.w = (v1.w-mu)*rs*gw1.w + bw1.w;
    *(float4*)&orow[d0] = o0;
    *(float4*)&orow[d1] = o1;
    *(half2*)&ohrow[d0]   = __floats2half2_rn(o0.x, o0.y);
    *(half2*)&ohrow[d0+2] = __floats2half2_rn(o0.z, o0.w);
    *(half2*)&ohrow[d1]   = __floats2half2_rn(o1.x, o1.y);
    *(half2*)&ohrow[d1+2] = __floats2half2_rn(o1.z, o1.w);
}

// ---------------- epilogues ----------------
// EPI 0: QKV scatter (fp16)  1: +b+res -> g_s (fp32)  2: gelu -> g_hidden (fp16)  3: +y -> out
template<int EPI>
__device__ __forceinline__ void epi_store(int gm, int gn, float v0, float v1,
                                          const float* __restrict__ biasN,
                                          const float* __restrict__ e0,
                                          float* __restrict__ outp) {
    v0 += biasN[gn]; v1 += biasN[gn+1];
    if constexpr (EPI == 0) {
        int part = gn >> 8, rem = gn & 255, h = rem >> 5, dk = rem & 31;
        int p = gm & 63, bt = gm >> 6;
        __half* dst = (part == 0) ? g_q : (part == 1 ? g_k : g_v);
        *(half2*)&dst[(((size_t)bt*HH + h)*PP + p)*DKK + dk] = __floats2half2_rn(v0, v1);
    } else if constexpr (EPI == 1) {
        int b = gm >> 15, t = (gm >> 6) & 511, p = gm & 63;
        float2 xr = *(const float2*)&e0[(((size_t)(b*PP + p))*TT + t)*DD + gn];
        *(float2*)&g_s[(size_t)gm*DD + gn] = make_float2(v0 + xr.x, v1 + xr.y);
    } else if constexpr (EPI == 2) {
        float g0 = 0.5f * v0 * (1.0f + erff(v0 * 0.70710678118654752f));
        float g1v = 0.5f * v1 * (1.0f + erff(v1 * 0.70710678118654752f));
        *(half2*)&g_hidden[(size_t)gm*FFF + gn] = __floats2half2_rn(g0, g1v);
    } else {
        float2 y = *(const float2*)&g_yn[(size_t)gm*DD + gn];
        int b = gm >> 15, t = (gm >> 6) & 511, p = gm & 63;
        *(float2*)&outp[(((size_t)(b*PP + p))*TT + t)*DD + gn] = make_float2(y.x + v0, y.y + v1);
    }
}

// ---------------- fp16 GEMM: C[M,N] = A[M,K] * W^T[N,K], fused epilogue ----------------
// BM=128, BN=128, BK=32, 3-stage cp.async ring, 256 threads, warp tile 64x32,
// m16n8k16 fp16 MMA with fp32 accumulate. Both operands row-major [rows][K] fp16.
#define GBM 128
#define GBN 128
#define GBK 32
#define TS_STRIDE 40    // halves; 80B row stride -> ldmatrix pieces conflict-free
#define TS_STAGE (128 * TS_STRIDE)
#define GEMM_SMEM_BYTES (6 * TS_STAGE * 2)

template<int EPI>
__global__ void __launch_bounds__(256, 2) gemm_kernel(
    const float* __restrict__ biasN, const float* __restrict__ e0,
    float* __restrict__ outp, int M, int N, int K) {
    const __half* A = (EPI == 0) ? g_xn : (EPI == 1) ? g_o : (EPI == 2) ? g_ynh : g_hidden;
    const __half* W = (EPI == 0) ? g_wq : (EPI == 1) ? g_wo : (EPI == 2) ? g_w1 : g_w2;  // [N][K]
    extern __shared__ __half smem[];
    __half* As = smem;                 // [3][128][40]  rows = m
    __half* Bs = smem + 3 * TS_STAGE;  // [3][128][40]  rows = n

    int tid = threadIdx.x;
    int bm = blockIdx.y * GBM, bn = blockIdx.x * GBN;

    auto load_stage = [&](int s, int kt) {
        __half* as = As + s * TS_STAGE;
        __half* bs = Bs + s * TS_STAGE;
#pragma unroll
        for (int i = 0; i < 2; i++) {       // A: 128 rows x 32 halves (4 x 16B per row)
            int f = tid + i * 256;
            int row = f >> 2, c8 = (f & 3) * 8;
            cpa16(smem_u32(&as[row * TS_STRIDE + c8]), A + (size_t)(bm + row) * K + kt * GBK + c8);
        }
#pragma unroll
        for (int i = 0; i < 2; i++) {       // B: 128 n-rows x 32 halves
            int f = tid + i * 256;
            int row = f >> 2, c8 = (f & 3) * 8;
            cpa16(smem_u32(&bs[row * TS_STRIDE + c8]), W + (size_t)(bn + row) * K + kt * GBK + c8);
        }
        asm volatile("cp.async.commit_group;");
    };

    float acc[4][4][4];
#pragma unroll
    for (int i = 0; i < 4; i++)
#pragma unroll
        for (int j = 0; j < 4; j++)
#pragma unroll
            for (int l = 0; l < 4; l++) acc[i][j][l] = 0.0f;

    int lane = tid & 31, wid = tid >> 5;
    int wm = (wid & 1) * 64, wn = (wid >> 1) * 32;
    int g = lane >> 2, tg = lane & 3;
    // ldmatrix lane addressing
    int rA = wm + (lane & 15);            // A rows; k-offset (lane>>4)*8
    int kaoff = (lane >> 4) * 8;
    int nB = wn + (lane & 7) + ((lane >> 4) & 1) * 8;   // + p2*16
    int kboff = ((lane >> 3) & 1) * 8;

    int nk = K / GBK;
    load_stage(0, 0);
    load_stage(1, 1);
    for (int kt = 0; kt < nk; kt++) {
        if (kt + 1 < nk) asm volatile("cp.async.wait_group 1;");
        else             asm volatile("cp.async.wait_group 0;");
        __syncthreads();
        if (kt + 2 < nk) load_stage((kt + 2) % 3, kt + 2);
        uint32_t a_st = smem_u32(As + (kt % 3) * TS_STAGE);
        uint32_t b_st = smem_u32(Bs + (kt % 3) * TS_STAGE);
#pragma unroll
        for (int ks = 0; ks < 2; ks++) {
            int kk = ks * 16;
            uint32_t af[4][4];
#pragma unroll
            for (int mt = 0; mt < 4; mt++)
                ldsm4(af[mt], a_st + (uint32_t)(((rA + mt * 16) * TS_STRIDE) + kk + kaoff) * 2);
            uint32_t bf[4][2];
#pragma unroll
            for (int p2 = 0; p2 < 2; p2++) {
                uint32_t br[4];
                ldsm4(br, b_st + (uint32_t)(((nB + p2 * 16) * TS_STRIDE) + kk + kboff) * 2);
                bf[2*p2][0] = br[0]; bf[2*p2][1] = br[1];
                bf[2*p2+1][0] = br[2]; bf[2*p2+1][1] = br[3];
            }
#pragma unroll
            for (int mt = 0; mt < 4; mt++)
#pragma unroll
                for (int nt = 0; nt < 4; nt++)
                    mma_f16(acc[mt][nt], af[mt], bf[nt]);
        }
    }

#pragma unroll
    for (int mt = 0; mt < 4; mt++)
#pragma unroll
        for (int nt = 0; nt < 4; nt++) {
            int gn = bn + wn + nt * 8 + tg * 2;
            int r0 = bm + wm + mt * 16 + g;
            epi_store<EPI>(r0,     gn, acc[mt][nt][0], acc[mt][nt][1], biasN, e0, outp);
            epi_store<EPI>(r0 + 8, gn, acc[mt][nt][2], acc[mt][nt][3], biasN, e0, outp);
        }
}

// ---------------- attention: one CTA per (b,t,h), fp16 MMA ----------------
__global__ void __launch_bounds__(128) attn_kernel() {
    __shared__ __half Qs[64][40], Ks[64][40], Vs[64][40];
    __shared__ __half Ss[64][72];
    int bth = blockIdx.x;
    int h = bth & 7, bt = bth >> 3, b = bt >> 9;
    size_t base = ((size_t)bt * HH + h) * PP * DKK;
    const uint4* Qg = (const uint4*)(g_q + base);   // 4 x 16B per 32-half row
    const uint4* Kg = (const uint4*)(g_k + base);
    const uint4* Vg = (const uint4*)(g_v + base);
    int tid = threadIdx.x;
    for (int i = tid; i < 256; i += 128) {
        int r = i >> 2, c8 = (i & 3) * 8;
        *(uint4*)&Qs[r][c8] = Qg[i];
        *(uint4*)&Ks[r][c8] = Kg[i];
        *(uint4*)&Vs[r][c8] = Vg[i];
    }
    __syncthreads();

    int lane = tid & 31, wid = tid >> 5;
    int g = lane >> 2, tg = lane & 3;
    int mb = wid * 16;

    // ldmatrix lane addressing
    int rA = mb + (lane & 15);
    int kaoff = (lane >> 4) * 8;
    int nB = (lane & 7) + ((lane >> 4) & 1) * 8;    // + nt2*16
    int kboff = ((lane >> 3) & 1) * 8;
    uint32_t qs_b = smem_u32(&Qs[0][0]);
    uint32_t ks_b = smem_u32(&Ks[0][0]);
    uint32_t vs_b = smem_u32(&Vs[0][0]);
    uint32_t ss_b = smem_u32(&Ss[0][0]);

    float acc[8][4];
#pragma unroll
    for (int i = 0; i < 8; i++)
#pragma unroll
        for (int j = 0; j < 4; j++) acc[i][j] = 0.0f;

    // S = Q @ K^T  (K=32 -> 2 ks steps)
#pragma unroll
    for (int ks = 0; ks < 2; ks++) {
        int kk = ks * 16;
        uint32_t af[4];
        ldsm4(af, qs_b + (uint32_t)(rA * 40 + kk + kaoff) * 2);
#pragma unroll
        for (int nt2 = 0; nt2 < 4; nt2++) {
            uint32_t br[4];
            ldsm4(br, ks_b + (uint32_t)((nB + nt2 * 16) * 40 + kk + kboff) * 2);
            uint32_t b0[2] = {br[0], br[1]}, b1[2] = {br[2], br[3]};
            mma_f16(acc[2*nt2],     af, b0);
            mma_f16(acc[2*nt2 + 1], af, b1);
        }
    }

    // softmax (fp32), bias from global (L2-resident, reused across T)
    int rowA = mb + g, rowB = rowA + 8;
    const float* bA = g_bias + (((size_t)b * HH + h) * PP + rowA) * PP;
    const float* bBr = bA + 8 * PP;
    const float sc = 0.17677669529663687f;  // 1/sqrt(32)
    float mA = -1e30f, mB = -1e30f;
#pragma unroll
    for (int nt = 0; nt < 8; nt++) {
        int c = nt * 8 + tg * 2;
        acc[nt][0] = acc[nt][0] * sc + bA[c];
        acc[nt][1] = acc[nt][1] * sc + bA[c + 1];
        acc[nt][2] = acc[nt][2] * sc + bBr[c];
        acc[nt][3] = acc[nt][3] * sc + bBr[c + 1];
        mA = fmaxf(mA, fmaxf(acc[nt][0], acc[nt][1]));
        mB = fmaxf(mB, fmaxf(acc[nt][2], acc[nt][3]));
    }
    mA = fmaxf(mA, __shfl_xor_sync(0xffffffffu, mA, 1));
    mA = fmaxf(mA, __shfl_xor_sync(0xffffffffu, mA, 2));
    mB = fmaxf(mB, __shfl_xor_sync(0xffffffffu, mB, 1));
    mB = fmaxf(mB, __shfl_xor_sync(0xffffffffu, mB, 2));
    float sA = 0.0f, sB = 0.0f;
#pragma unroll
    for (int nt = 0; nt < 8; nt++) {
        acc[nt][0] = expf(acc[nt][0] - mA);
        acc[nt][1] = expf(acc[nt][1] - mA);
        acc[nt][2] = expf(acc[nt][2] - mB);
        acc[nt][3] = expf(acc[nt][3] - mB);
        sA += acc[nt][0] + acc[nt][1];
        sB += acc[nt][2] + acc[nt][3];
    }
    sA += __shfl_xor_sync(0xffffffffu, sA, 1);
    sA += __shfl_xor_sync(0xffffffffu, sA, 2);
    sB += __shfl_xor_sync(0xffffffffu, sB, 1);
    sB += __shfl_xor_sync(0xffffffffu, sB, 2);
    float iA = 1.0f / sA, iB = 1.0f / sB;
#pragma unroll
    for (int nt = 0; nt < 8; nt++) {
        int c = nt * 8 + tg * 2;
        *(half2*)&Ss[rowA][c] = __floats2half2_rn(acc[nt][0] * iA, acc[nt][1] * iA);
        *(half2*)&Ss[rowB][c] = __floats2half2_rn(acc[nt][2] * iB, acc[nt][3] * iB);
    }
    __syncwarp();

    // O = P @ V  (K=64 -> 4 ks steps; V via ldmatrix.trans)
    float accO[4][4];
#pragma unroll
    for (int i = 0; i < 4; i++)
#pragma unroll
        for (int j = 0; j < 4; j++) accO[i][j] = 0.0f;
#pragma unroll
    for (int ks = 0; ks < 4; ks++) {
        int kk = ks * 16;
        uint32_t af[4];
        ldsm4(af, ss_b + (uint32_t)(rA * 72 + kk + kaoff) * 2);
#pragma unroll
        for (int nt2 = 0; nt2 < 2; nt2++) {
            uint32_t br[4];
            // trans: rows = k (p-index), cols = n (dk)
            int vr = kk + (lane & 7) + ((lane >> 3) & 1) * 8;
            int vc = nt2 * 16 + ((lane >> 4) & 1) * 8;
            ldsm4t(br, vs_b + (uint32_t)(vr * 40 + vc) * 2);
            uint32_t b0[2] = {br[0], br[1]}, b1[2] = {br[2], br[3]};
            mma_f16(accO[2*nt2],     af, b0);
            mma_f16(accO[2*nt2 + 1], af, b1);
        }
    }
#pragma unroll
    for (int nt = 0; nt < 4; nt++) {
        int dk = nt * 8 + tg * 2;
        *(half2*)&g_o[((size_t)bt * PP + rowA) * DD + h * 32 + dk] =
            __floats2half2_rn(accO[nt][0], accO[nt][1]);
        *(half2*)&g_o[((size_t)bt * PP + rowB) * DD + h * 32 + dk] =
            __floats2half2_rn(accO[nt][2], accO[nt][3]);
    }
}

// ---------------- launch ----------------
extern "C" void kernel_launch(void* const* d_in, const int* in_sizes, int n_in,
                              void* d_out, int out_size) {
    const float* x     = (const float*)d_in[0];
    const float* pos   = (const float*)d_in[1];
    const float* w_qkv = (const float*)d_in[2];
    const float* b_qkv = (const float*)d_in[3];
    const float* w_out = (const float*)d_in[4];
    const float* b_out = (const float*)d_in[5];
    const float* w_ff1 = (const float*)d_in[6];
    const float* b_ff1 = (const float*)d_in[7];
    const float* w_ff2 = (const float*)d_in[8];
    const float* b_ff2 = (const float*)d_in[9];
    const float* w_rel = (const float*)d_in[10];
    const float* g1    = (const float*)d_in[11];
    const float* be1   = (const float*)d_in[12];
    const float* g2    = (const float*)d_in[13];
    const float* be2   = (const float*)d_in[14];
    float* out = (float*)d_out;

    cudaFuncSetAttribute(gemm_kernel<0>, cudaFuncAttributeMaxDynamicSharedMemorySize, GEMM_SMEM_BYTES);
    cudaFuncSetAttribute(gemm_kernel<1>, cudaFuncAttributeMaxDynamicSharedMemorySize, GEMM_SMEM_BYTES);
    cudaFuncSetAttribute(gemm_kernel<2>, cudaFuncAttributeMaxDynamicSharedMemorySize, GEMM_SMEM_BYTES);
    cudaFuncSetAttribute(gemm_kernel<3>, cudaFuncAttributeMaxDynamicSharedMemorySize, GEMM_SMEM_BYTES);

    __half *p_wq, *p_wo, *p_w1, *p_w2;
    cudaGetSymbolAddress((void**)&p_wq, g_wq);
    cudaGetSymbolAddress((void**)&p_wo, g_wo);
    cudaGetSymbolAddress((void**)&p_w1, g_w1);
    cudaGetSymbolAddress((void**)&p_w2, g_w2);

    // transpose + fp16-round weights: dst[n][k] = half(src[k][n])
    cvtw_t<<<dim3(DD/32, 3*DD/32), dim3(32, 8)>>>(w_qkv, p_wq, DD, 3*DD);
    cvtw_t<<<dim3(DD/32, DD/32),   dim3(32, 8)>>>(w_out, p_wo, DD, DD);
    cvtw_t<<<dim3(DD/32, FFF/32),  dim3(32, 8)>>>(w_ff1, p_w1, DD, FFF);
    cvtw_t<<<dim3(FFF/32, DD/32),  dim3(32, 8)>>>(w_ff2, p_w2, FFF, DD);

    relbias_kernel<<<BB * PP, 64>>>(pos, w_rel);
    ln1_kernel<<<M_TOK / 8, 256>>>(x, g1, be1);
    gemm_kernel<0><<<dim3(3 * DD / GBN, M_TOK / GBM), 256, GEMM_SMEM_BYTES>>>(b_qkv, nullptr, nullptr, M_TOK, 3 * DD, DD);
    attn_kernel<<<BB * TT * HH, 128>>>();
    gemm_kernel<1><<<dim3(DD / GBN, M_TOK / GBM), 256, GEMM_SMEM_BYTES>>>(b_out, x, nullptr, M_TOK, DD, DD);
    ln2_kernel<<<M_TOK / 8, 256>>>(g2, be2);
    gemm_kernel<2><<<dim3(FFF / GBN, M_TOK / GBM), 256, GEMM_SMEM_BYTES>>>(b_ff1, nullptr, nullptr, M_TOK, FFF, DD);
    gemm_kernel<3><<<dim3(DD / GBN, M_TOK / GBM), 256, GEMM_SMEM_BYTES>>>(b_ff2, nullptr, out, M_TOK, DD, FFF);
}